// round 8
// baseline (speedup 1.0000x reference)
#include <cuda_runtime.h>
#include <cuda_bf16.h>
#include <math.h>
#include <stdint.h>

#define NN 50000
#define NE 200000
#define ND 160
#define ED 64
#define RD 8
#define HD 256
#define EH 128

// ---------------- scratch (device globals; no runtime allocation) ----------
__device__ float g_init_edge[NE*ED];
__device__ float g_edge_lat [NE*ED];
__device__ float g_new_edge [NE*ED];
__device__ float g_node_lat [NN*ND];
__device__ float g_msg      [NE*HD];
__device__ float g_logit    [NE];
__device__ float g_P        [(size_t)NN*768];   // [P1|P2|P3] per node
__device__ float g_Pbase    [(size_t)NN*768];   // x-part of P (iteration-invariant)
__device__ float g_Penc     [(size_t)NN*256];   // [enc1|enc2] per node
// packed bf16 hi/lo weight tables (u32 = 2 bf16 along K), K-major [n][k/2]
__device__ uint32_t gWPh[768*160], gWPl[768*160];   // P gemm, K=320 (words 0:80 x-part, 80:160 node-part)
__device__ uint32_t gWEh[256*80],  gWEl[256*80];    // enc gemm, K=160
__device__ uint32_t gB1h[256*64],  gB1l[256*64];    // edge phase1 tail, K=128
__device__ uint32_t gB2h[64*128],  gB2l[64*128];    // edge phase2, K=256
__device__ uint32_t gB3h[256*32],  gB3l[256*32];    // edge phase3 tail, K=64
__device__ int   g_deg      [NN];
__device__ int   g_rowptr   [NN+1];
__device__ int   g_fill     [NN];
__device__ int   g_eids     [NE];
__device__ int   g_part     [64];

// ---------------- bf16 split helpers ----------------------------------------
__device__ __forceinline__ void split2(float x, float y, uint32_t& hi, uint32_t& lo){
    __nv_bfloat162 h = __floats2bfloat162_rn(x, y);
    hi = *(uint32_t*)&h;
    float rx = x - __bfloat162float(h.x);
    float ry = y - __bfloat162float(h.y);
    __nv_bfloat162 l = __floats2bfloat162_rn(rx, ry);
    lo = *(uint32_t*)&l;
}
__device__ __forceinline__ void mma_bf16(
    float& c0, float& c1, float& c2, float& c3,
    uint32_t a0, uint32_t a1, uint32_t a2, uint32_t a3, uint32_t b0, uint32_t b1)
{
    asm volatile(
        "mma.sync.aligned.m16n8k16.row.col.f32.bf16.bf16.f32 "
        "{%0,%1,%2,%3}, {%4,%5,%6,%7}, {%8,%9}, {%0,%1,%2,%3};"
        : "+f"(c0), "+f"(c1), "+f"(c2), "+f"(c3)
        : "r"(a0), "r"(a1), "r"(a2), "r"(a3), "r"(b0), "r"(b1));
}

// ---------------- CSR build --------------------------------------------------
__global__ void k_hist(const int* __restrict__ row){
    int e = blockIdx.x*blockDim.x + threadIdx.x;
    if (e < NE) atomicAdd(&g_deg[row[e]], 1);
}

__global__ void k_scan1(){
    __shared__ int ss[256];
    int b = blockIdx.x, base = b*1024, tid = threadIdx.x;
    int v[4], tsum = 0;
#pragma unroll
    for (int r = 0; r < 4; r++){
        int idx = base + tid*4 + r;
        v[r] = (idx < NN) ? g_deg[idx] : 0;
        tsum += v[r];
    }
    ss[tid] = tsum; __syncthreads();
    for (int off = 1; off < 256; off <<= 1){
        int add = (tid >= off) ? ss[tid-off] : 0;
        __syncthreads();
        ss[tid] += add;
        __syncthreads();
    }
    int run = ss[tid] - tsum;
#pragma unroll
    for (int r = 0; r < 4; r++){
        int idx = base + tid*4 + r;
        if (idx < NN) g_rowptr[idx] = run;
        run += v[r];
    }
    if (tid == 255) g_part[b] = ss[255];
}

__global__ void k_scan2(){
    if (threadIdx.x == 0){
        int run = 0;
        for (int i = 0; i < 49; i++){ int t = g_part[i]; g_part[i] = run; run += t; }
    }
}

__global__ void k_scan3(){
    int i = blockIdx.x*blockDim.x + threadIdx.x;
    if (i < NN) g_rowptr[i] += g_part[i >> 10];
    if (i == 0) g_rowptr[NN] = NE;
}

__global__ void k_scatter(const int* __restrict__ row){
    int e = blockIdx.x*blockDim.x + threadIdx.x;
    if (e < NE){
        int p = atomicAdd(&g_fill[row[e]], 1);
        g_eids[p] = e;
    }
}

// ---------------- pack all weight tables (bf16 hi/lo, K-major) ---------------
__global__ void k_prep(const float* __restrict__ eW1, const float* __restrict__ mW1,
                       const float* __restrict__ encW1, const float* __restrict__ eW2)
{
    int i = blockIdx.x*blockDim.x + threadIdx.x;
    if (i < 768*160){
        int n = i/160, w = i - n*160, k = w*2;
        float f0, f1;
        if (n < 256){ f0 = eW1[k*256+n]; f1 = eW1[(k+1)*256+n]; }
        else if (n < 512){ int nn = n-256; f0 = eW1[(320+k)*256+nn]; f1 = eW1[(321+k)*256+nn]; }
        else { int nn = n-512; f0 = mW1[k*256+nn]; f1 = mW1[(k+1)*256+nn]; }
        split2(f0, f1, gWPh[i], gWPl[i]);
    }
    if (i < 256*80){
        int n = i/80, w = i - n*80, k = w*2;
        float f0, f1;
        if (n < 128){ f0 = encW1[k*128+n]; f1 = encW1[(k+1)*128+n]; }
        else { int nn = n-128; f0 = encW1[(160+k)*128+nn]; f1 = encW1[(161+k)*128+nn]; }
        split2(f0, f1, gWEh[i], gWEl[i]);
    }
    if (i < 256*64){
        int n = i/64, w = i - n*64, k = w*2;
        split2(eW1[(640+k)*256+n], eW1[(641+k)*256+n], gB1h[i], gB1l[i]);
    }
    if (i < 64*128){
        int n = i/128, w = i - n*128, k = w*2;
        split2(eW2[k*64+n], eW2[(k+1)*64+n], gB2h[i], gB2l[i]);
    }
    if (i < 256*32){
        int n = i/32, w = i - n*32, k = w*2;
        split2(mW1[(320+k)*256+n], mW1[(321+k)*256+n], gB3h[i], gB3l[i]);
    }
}

// ---------------- bf16 3-split dense GEMM (m16n8k16) -------------------------
__global__ __launch_bounds__(256,2) void k_gemm_bf(
    const float* __restrict__ A0, const float* __restrict__ A1,
    const uint32_t* __restrict__ Bh, const uint32_t* __restrict__ Bl,
    int K, int bstrW,
    float* __restrict__ out, int ostride, const float* __restrict__ base)
{
    __shared__ uint32_t sAh[128*20], sAl[128*20], sBh[128*20], sBl[128*20];
    const int tid = threadIdx.x, wid = tid>>5, lane = tid&31;
    const int gid = lane>>2, tq = lane&3;
    const int warp_m = (wid & 1)*64, warp_n = (wid >> 1)*32;
    const int m0 = blockIdx.x*128, n0 = blockIdx.y*128;

    float c[4][4][4];
#pragma unroll
    for (int i = 0; i < 4; i++)
#pragma unroll
        for (int j = 0; j < 4; j++)
#pragma unroll
            for (int r = 0; r < 4; r++) c[i][j][r] = 0.f;

    const int nk = K >> 5;
    for (int ch = 0; ch < nk; ch++){
        const int kc = ch*32;
        const float* A = (kc < 160) ? A0 : A1;
        const int ac = (kc < 160) ? kc : (kc - 160);
#pragma unroll
        for (int p = 0; p < 4; p++){
            int lin = tid + p*256;
            int row = lin>>3, f4 = lin&7;
            int gm = m0 + row;
            float4 v = make_float4(0.f,0.f,0.f,0.f);
            if (gm < NN) v = *(const float4*)&A[(size_t)gm*ND + ac + f4*4];
            uint32_t h0,l0,h1,l1;
            split2(v.x, v.y, h0, l0);
            split2(v.z, v.w, h1, l1);
            sAh[row*20 + f4*2]   = h0; sAh[row*20 + f4*2+1] = h1;
            sAl[row*20 + f4*2]   = l0; sAl[row*20 + f4*2+1] = l1;
        }
#pragma unroll
        for (int p = 0; p < 2; p++){
            int lin = tid + p*256;
            int row = lin>>2, q = lin&3;
            size_t gofs = (size_t)(n0+row)*bstrW + (kc>>1) + q*4;
            *(uint4*)&sBh[row*20 + q*4] = *(const uint4*)&Bh[gofs];
            *(uint4*)&sBl[row*20 + q*4] = *(const uint4*)&Bl[gofs];
        }
        __syncthreads();
#pragma unroll
        for (int s = 0; s < 2; s++){
            const int kb = s*8 + tq;
            uint32_t bh0[4], bh1[4], bl0[4], bl1[4];
#pragma unroll
            for (int nt = 0; nt < 4; nt++){
                int nr = warp_n + nt*8 + gid;
                bh0[nt] = sBh[nr*20 + kb]; bh1[nt] = sBh[nr*20 + kb + 4];
                bl0[nt] = sBl[nr*20 + kb]; bl1[nt] = sBl[nr*20 + kb + 4];
            }
#pragma unroll
            for (int mt = 0; mt < 4; mt++){
                int ar = warp_m + mt*16 + gid;
                uint32_t ah0 = sAh[ar*20+kb],     ah1 = sAh[(ar+8)*20+kb];
                uint32_t ah2 = sAh[ar*20+kb+4],   ah3 = sAh[(ar+8)*20+kb+4];
                uint32_t al0 = sAl[ar*20+kb],     al1 = sAl[(ar+8)*20+kb];
                uint32_t al2 = sAl[ar*20+kb+4],   al3 = sAl[(ar+8)*20+kb+4];
#pragma unroll
                for (int nt = 0; nt < 4; nt++){
                    mma_bf16(c[mt][nt][0], c[mt][nt][1], c[mt][nt][2], c[mt][nt][3],
                             ah0, ah1, ah2, ah3, bh0[nt], bh1[nt]);
                    mma_bf16(c[mt][nt][0], c[mt][nt][1], c[mt][nt][2], c[mt][nt][3],
                             ah0, ah1, ah2, ah3, bl0[nt], bl1[nt]);
                    mma_bf16(c[mt][nt][0], c[mt][nt][1], c[mt][nt][2], c[mt][nt][3],
                             al0, al1, al2, al3, bh0[nt], bh1[nt]);
                }
            }
        }
        __syncthreads();
    }

#pragma unroll
    for (int mt = 0; mt < 4; mt++){
        int r0 = m0 + warp_m + mt*16 + gid;
        int r1 = r0 + 8;
#pragma unroll
        for (int nt = 0; nt < 4; nt++){
            int gn = n0 + warp_n + nt*8 + tq*2;
            if (r0 < NN){
                float2 v = make_float2(c[mt][nt][0], c[mt][nt][1]);
                if (base){ float2 b = *(const float2*)&base[(size_t)r0*ostride + gn]; v.x += b.x; v.y += b.y; }
                *(float2*)&out[(size_t)r0*ostride + gn] = v;
            }
            if (r1 < NN){
                float2 v = make_float2(c[mt][nt][2], c[mt][nt][3]);
                if (base){ float2 b = *(const float2*)&base[(size_t)r1*ostride + gn]; v.x += b.x; v.y += b.y; }
                *(float2*)&out[(size_t)r1*ostride + gn] = v;
            }
        }
    }
}

// ---------------- fused edge kernel on tensor cores (128 edges/block) --------
// Full-K B staging per phase: one staging pass + one long MMA run per phase.
// smem layout (u32 words), total 52224 w = 208,896 B:
//  phase1: Ah@0[128x68] Al@8704 | B1h@17408[256x68] B1l@34816
//  phase2: Hh@0[128x132] Hl@16896 | B2h@33792[64x132] B2l@42240
//  phase3: NEh@0[128x36] NEl@4608 | B3h@9216[256x36] B3l@18432
__global__ __launch_bounds__(512,1) void k_edge_tc(
    const int* __restrict__ row, const int* __restrict__ col,
    const float* __restrict__ eb1, const float* __restrict__ eb2,
    const float* __restrict__ mb1, const float* __restrict__ attv)
{
    extern __shared__ uint32_t esm[];
    uint32_t* Ah  = esm;
    uint32_t* Al  = esm + 8704;
    uint32_t* B1h = esm + 17408;
    uint32_t* B1l = esm + 34816;
    uint32_t* Hh  = esm;
    uint32_t* Hl  = esm + 16896;
    uint32_t* B2h = esm + 33792;
    uint32_t* B2l = esm + 42240;
    uint32_t* NEh = esm;
    uint32_t* NEl = esm + 4608;
    uint32_t* B3h = esm + 9216;
    uint32_t* B3l = esm + 18432;
    __shared__ int sR[128], sC[128];
    __shared__ float sAtt[256];
    __shared__ float sLog[128];

    const int tid = threadIdx.x, wid = tid>>5, lane = tid&31;
    const int gid = lane>>2, tq = lane&3;
    const int warp_m  = (wid & 1)*64;
    const int warp_n  = (wid >> 1)*32;
    const int warp_n2 = (wid >> 1)*8;
    const int e0 = blockIdx.x*128;

    if (tid < 128){
        int ge = e0 + tid;
        sR[tid] = (ge < NE) ? row[ge] : 0;
        sC[tid] = (ge < NE) ? col[ge] : 0;
        sLog[tid] = 0.f;
    }
    if (tid < 256) sAtt[tid] = attv[tid];
    __syncthreads();

    // ---- phase 1: stage A + full B1, init C from P gathers ------------------
    for (int lin = tid; lin < 8192; lin += 512){
        int r = lin>>6, w = lin&63, k = w*2;
        float2 v = make_float2(0.f, 0.f);
        if (e0 + r < NE)
            v = (k < 64) ? *(const float2*)&g_init_edge[(size_t)(e0+r)*ED + k]
                         : *(const float2*)&g_edge_lat [(size_t)(e0+r)*ED + (k-64)];
        split2(v.x, v.y, Ah[r*68+w], Al[r*68+w]);
    }
    for (int lin = tid; lin < 4096; lin += 512){
        int r = lin>>4, q = lin&15;
        size_t gofs = (size_t)r*64 + q*4;
        *(uint4*)&B1h[r*68 + q*4] = *(const uint4*)&gB1h[gofs];
        *(uint4*)&B1l[r*68 + q*4] = *(const uint4*)&gB1l[gofs];
    }
    float c1[4][4][4];
#pragma unroll
    for (int mt = 0; mt < 4; mt++){
        int rA = warp_m + mt*16 + gid, rB = rA + 8;
        size_t prA = (size_t)sR[rA]*768, pcA = (size_t)sC[rA]*768;
        size_t prB = (size_t)sR[rB]*768, pcB = (size_t)sC[rB]*768;
#pragma unroll
        for (int nt = 0; nt < 4; nt++){
            int cn = warp_n + nt*8 + tq*2;
            float2 b  = *(const float2*)&eb1[cn];
            float2 a1 = *(const float2*)&g_P[prA + cn];
            float2 a2 = *(const float2*)&g_P[pcA + 256 + cn];
            float2 a3 = *(const float2*)&g_P[prB + cn];
            float2 a4 = *(const float2*)&g_P[pcB + 256 + cn];
            c1[mt][nt][0] = a1.x + a2.x + b.x;
            c1[mt][nt][1] = a1.y + a2.y + b.y;
            c1[mt][nt][2] = a3.x + a4.x + b.x;
            c1[mt][nt][3] = a3.y + a4.y + b.y;
        }
    }
    __syncthreads();

#pragma unroll
    for (int s = 0; s < 8; s++){
        int ka = s*8 + tq;
        uint32_t bh0[4], bh1[4], bl0[4], bl1[4];
#pragma unroll
        for (int nt = 0; nt < 4; nt++){
            int nr = warp_n + nt*8 + gid;
            bh0[nt] = B1h[nr*68+ka]; bh1[nt] = B1h[nr*68+ka+4];
            bl0[nt] = B1l[nr*68+ka]; bl1[nt] = B1l[nr*68+ka+4];
        }
#pragma unroll
        for (int mt = 0; mt < 4; mt++){
            int ar = warp_m + mt*16 + gid;
            uint32_t ah0 = Ah[ar*68+ka],   ah1 = Ah[(ar+8)*68+ka];
            uint32_t ah2 = Ah[ar*68+ka+4], ah3 = Ah[(ar+8)*68+ka+4];
            uint32_t al0 = Al[ar*68+ka],   al1 = Al[(ar+8)*68+ka];
            uint32_t al2 = Al[ar*68+ka+4], al3 = Al[(ar+8)*68+ka+4];
#pragma unroll
            for (int nt = 0; nt < 4; nt++){
                mma_bf16(c1[mt][nt][0],c1[mt][nt][1],c1[mt][nt][2],c1[mt][nt][3],
                         ah0,ah1,ah2,ah3, bh0[nt],bh1[nt]);
                mma_bf16(c1[mt][nt][0],c1[mt][nt][1],c1[mt][nt][2],c1[mt][nt][3],
                         ah0,ah1,ah2,ah3, bl0[nt],bl1[nt]);
                mma_bf16(c1[mt][nt][0],c1[mt][nt][1],c1[mt][nt][2],c1[mt][nt][3],
                         al0,al1,al2,al3, bh0[nt],bh1[nt]);
            }
        }
    }
    __syncthreads();

    // ---- write hidden (relu, bf16 split) + stage full B2 ---------------------
#pragma unroll
    for (int mt = 0; mt < 4; mt++){
        int rA = warp_m + mt*16 + gid, rB = rA + 8;
#pragma unroll
        for (int nt = 0; nt < 4; nt++){
            int wcol = (warp_n>>1) + nt*4 + tq;
            float v0 = fmaxf(c1[mt][nt][0], 0.f), v1 = fmaxf(c1[mt][nt][1], 0.f);
            float v2 = fmaxf(c1[mt][nt][2], 0.f), v3 = fmaxf(c1[mt][nt][3], 0.f);
            split2(v0, v1, Hh[rA*132+wcol], Hl[rA*132+wcol]);
            split2(v2, v3, Hh[rB*132+wcol], Hl[rB*132+wcol]);
        }
    }
    for (int lin = tid; lin < 2048; lin += 512){
        int r = lin>>5, q = lin&31;
        size_t gofs = (size_t)r*128 + q*4;
        *(uint4*)&B2h[r*132 + q*4] = *(const uint4*)&gB2h[gofs];
        *(uint4*)&B2l[r*132 + q*4] = *(const uint4*)&gB2l[gofs];
    }
    __syncthreads();

    // ---- phase 2 -------------------------------------------------------------
    float c2[4][4];
#pragma unroll
    for (int mt = 0; mt < 4; mt++){
        float2 b = *(const float2*)&eb2[warp_n2 + tq*2];
        c2[mt][0] = b.x; c2[mt][1] = b.y; c2[mt][2] = b.x; c2[mt][3] = b.y;
    }
#pragma unroll
    for (int s = 0; s < 16; s++){
        int ka = s*8 + tq;
        int nr = warp_n2 + gid;
        uint32_t bh0 = B2h[nr*132+ka], bh1 = B2h[nr*132+ka+4];
        uint32_t bl0 = B2l[nr*132+ka], bl1 = B2l[nr*132+ka+4];
#pragma unroll
        for (int mt = 0; mt < 4; mt++){
            int ar = warp_m + mt*16 + gid;
            uint32_t ah0 = Hh[ar*132+ka],   ah1 = Hh[(ar+8)*132+ka];
            uint32_t ah2 = Hh[ar*132+ka+4], ah3 = Hh[(ar+8)*132+ka+4];
            uint32_t al0 = Hl[ar*132+ka],   al1 = Hl[(ar+8)*132+ka];
            uint32_t al2 = Hl[ar*132+ka+4], al3 = Hl[(ar+8)*132+ka+4];
            mma_bf16(c2[mt][0],c2[mt][1],c2[mt][2],c2[mt][3], ah0,ah1,ah2,ah3, bh0,bh1);
            mma_bf16(c2[mt][0],c2[mt][1],c2[mt][2],c2[mt][3], ah0,ah1,ah2,ah3, bl0,bl1);
            mma_bf16(c2[mt][0],c2[mt][1],c2[mt][2],c2[mt][3], al0,al1,al2,al3, bh0,bh1);
        }
    }
    __syncthreads();

    // ---- write new_edge fp32 + NE pack + stage full B3 -----------------------
#pragma unroll
    for (int mt = 0; mt < 4; mt++){
        int rA = warp_m + mt*16 + gid, rB = rA + 8;
        int cn = warp_n2 + tq*2;
        int wcol = (warp_n2>>1) + tq;
        if (e0 + rA < NE)
            *(float2*)&g_new_edge[(size_t)(e0+rA)*ED + cn] = make_float2(c2[mt][0], c2[mt][1]);
        if (e0 + rB < NE)
            *(float2*)&g_new_edge[(size_t)(e0+rB)*ED + cn] = make_float2(c2[mt][2], c2[mt][3]);
        split2(c2[mt][0], c2[mt][1], NEh[rA*36+wcol], NEl[rA*36+wcol]);
        split2(c2[mt][2], c2[mt][3], NEh[rB*36+wcol], NEl[rB*36+wcol]);
    }
    for (int lin = tid; lin < 2048; lin += 512){
        int r = lin>>3, q = lin&7;
        size_t gofs = (size_t)r*32 + q*4;
        *(uint4*)&B3h[r*36 + q*4] = *(const uint4*)&gB3h[gofs];
        *(uint4*)&B3l[r*36 + q*4] = *(const uint4*)&gB3l[gofs];
    }

    // ---- phase 3 accumulator init from P gathers (no smem dep) ---------------
    float c3[4][4][4];
#pragma unroll
    for (int mt = 0; mt < 4; mt++){
        int rA = warp_m + mt*16 + gid, rB = rA + 8;
        size_t pcA = (size_t)sC[rA]*768, pcB = (size_t)sC[rB]*768;
#pragma unroll
        for (int nt = 0; nt < 4; nt++){
            int cn = warp_n + nt*8 + tq*2;
            float2 b  = *(const float2*)&mb1[cn];
            float2 a1 = *(const float2*)&g_P[pcA + 512 + cn];
            float2 a2 = *(const float2*)&g_P[pcB + 512 + cn];
            c3[mt][nt][0] = a1.x + b.x; c3[mt][nt][1] = a1.y + b.y;
            c3[mt][nt][2] = a2.x + b.x; c3[mt][nt][3] = a2.y + b.y;
        }
    }
    __syncthreads();

#pragma unroll
    for (int s = 0; s < 4; s++){
        int ka = s*8 + tq;
        uint32_t bh0[4], bh1[4], bl0[4], bl1[4];
#pragma unroll
        for (int nt = 0; nt < 4; nt++){
            int nr = warp_n + nt*8 + gid;
            bh0[nt] = B3h[nr*36+ka]; bh1[nt] = B3h[nr*36+ka+4];
            bl0[nt] = B3l[nr*36+ka]; bl1[nt] = B3l[nr*36+ka+4];
        }
#pragma unroll
        for (int mt = 0; mt < 4; mt++){
            int ar = warp_m + mt*16 + gid;
            uint32_t ah0 = NEh[ar*36+ka],   ah1 = NEh[(ar+8)*36+ka];
            uint32_t ah2 = NEh[ar*36+ka+4], ah3 = NEh[(ar+8)*36+ka+4];
            uint32_t al0 = NEl[ar*36+ka],   al1 = NEl[(ar+8)*36+ka];
            uint32_t al2 = NEl[ar*36+ka+4], al3 = NEl[(ar+8)*36+ka+4];
#pragma unroll
            for (int nt = 0; nt < 4; nt++){
                mma_bf16(c3[mt][nt][0],c3[mt][nt][1],c3[mt][nt][2],c3[mt][nt][3],
                         ah0,ah1,ah2,ah3, bh0[nt],bh1[nt]);
                mma_bf16(c3[mt][nt][0],c3[mt][nt][1],c3[mt][nt][2],c3[mt][nt][3],
                         ah0,ah1,ah2,ah3, bl0[nt],bl1[nt]);
                mma_bf16(c3[mt][nt][0],c3[mt][nt][1],c3[mt][nt][2],c3[mt][nt][3],
                         al0,al1,al2,al3, bh0[nt],bh1[nt]);
            }
        }
    }

    // epilogue: relu -> g_msg, attention partial dot, logit
    float pa[4][2];
#pragma unroll
    for (int mt = 0; mt < 4; mt++){ pa[mt][0] = 0.f; pa[mt][1] = 0.f; }
#pragma unroll
    for (int mt = 0; mt < 4; mt++){
        int rA = warp_m + mt*16 + gid, rB = rA + 8;
#pragma unroll
        for (int nt = 0; nt < 4; nt++){
            int cn = warp_n + nt*8 + tq*2;
            float av0 = sAtt[cn], av1 = sAtt[cn+1];
            float v0 = fmaxf(c3[mt][nt][0], 0.f), v1 = fmaxf(c3[mt][nt][1], 0.f);
            float v2 = fmaxf(c3[mt][nt][2], 0.f), v3 = fmaxf(c3[mt][nt][3], 0.f);
            if (e0 + rA < NE)
                *(float2*)&g_msg[(size_t)(e0+rA)*HD + cn] = make_float2(v0, v1);
            if (e0 + rB < NE)
                *(float2*)&g_msg[(size_t)(e0+rB)*HD + cn] = make_float2(v2, v3);
            pa[mt][0] += v0*av0 + v1*av1;
            pa[mt][1] += v2*av0 + v3*av1;
        }
    }
#pragma unroll
    for (int off = 1; off <= 2; off <<= 1){
#pragma unroll
        for (int mt = 0; mt < 4; mt++){
            pa[mt][0] += __shfl_xor_sync(0xffffffffu, pa[mt][0], off, 4);
            pa[mt][1] += __shfl_xor_sync(0xffffffffu, pa[mt][1], off, 4);
        }
    }
    if (tq == 0){
#pragma unroll
        for (int mt = 0; mt < 4; mt++){
            atomicAdd(&sLog[warp_m + mt*16 + gid],     pa[mt][0]);
            atomicAdd(&sLog[warp_m + mt*16 + gid + 8], pa[mt][1]);
        }
    }
    __syncthreads();
    if (tid < 128 && e0 + tid < NE){
        float p = sLog[tid];
        g_logit[e0+tid] = (p > 0.f) ? p : 0.2f*p;
    }
}

// ---------------- edge encoder tail: per-edge part (FFMA, small) -------------
__global__ __launch_bounds__(256,2) void k_enc_edge(
    const float* __restrict__ ea,
    const int* __restrict__ row, const int* __restrict__ col,
    const float* __restrict__ encW1, const float* __restrict__ encb1,
    const float* __restrict__ encW2, const float* __restrict__ encb2)
{
    __shared__ float As[64*9];
    __shared__ float Bs[16*64];
    __shared__ float Hid[64*132];
    __shared__ int sR[64], sC[64];

    const int e0 = blockIdx.x*64;
    const int tid = threadIdx.x, ty = tid>>4, tx = tid&15;
    if (tid < 64){ sR[tid] = row[e0+tid]; sC[tid] = col[e0+tid]; }
    __syncthreads();

    float c[4][8];
#pragma unroll
    for (int i = 0; i < 4; i++){
        int r = ty*4+i;
#pragma unroll
        for (int j = 0; j < 8; j++){
            int n = tx + 16*j;
            c[i][j] = g_Penc[(size_t)sR[r]*256 + n]
                    + g_Penc[(size_t)sC[r]*256 + 128 + n]
                    + encb1[n];
        }
    }
    for (int t = tid; t < 512; t += 256){
        int el = t>>3, kk = t&7;
        As[el*9+kk] = ea[(e0+el)*RD + kk];
    }
    for (int t = tid; t < 1024; t += 256){
        int kk = t>>7, n = t&127;
        Bs[t] = encW1[(320+kk)*EH + n];
    }
    __syncthreads();
#pragma unroll
    for (int kk = 0; kk < 8; kk++){
        float a0 = As[(ty*4+0)*9+kk], a1 = As[(ty*4+1)*9+kk];
        float a2 = As[(ty*4+2)*9+kk], a3 = As[(ty*4+3)*9+kk];
#pragma unroll
        for (int j = 0; j < 8; j++){
            float b = Bs[kk*128 + tx + 16*j];
            c[0][j] += a0*b; c[1][j] += a1*b; c[2][j] += a2*b; c[3][j] += a3*b;
        }
    }
    __syncthreads();
#pragma unroll
    for (int i = 0; i < 4; i++)
#pragma unroll
        for (int j = 0; j < 8; j++){
            int n = tx + 16*j;
            Hid[(ty*4+i)*132 + n] = fmaxf(c[i][j], 0.f);
        }
    __syncthreads();

    float c2[4][4];
#pragma unroll
    for (int i = 0; i < 4; i++)
#pragma unroll
        for (int j = 0; j < 4; j++) c2[i][j] = encb2[tx+16*j];

    for (int kc = 0; kc < 128; kc += 16){
        for (int t = tid; t < 1024; t += 256){
            int kk = t>>6, n = t&63;
            Bs[t] = encW2[(kc+kk)*ED + n];
        }
        __syncthreads();
#pragma unroll
        for (int kk = 0; kk < 16; kk++){
            float a0 = Hid[(ty*4+0)*132 + kc+kk], a1 = Hid[(ty*4+1)*132 + kc+kk];
            float a2 = Hid[(ty*4+2)*132 + kc+kk], a3 = Hid[(ty*4+3)*132 + kc+kk];
#pragma unroll
            for (int j = 0; j < 4; j++){
                float b = Bs[kk*64 + tx + 16*j];
                c2[0][j] += a0*b; c2[1][j] += a1*b; c2[2][j] += a2*b; c2[3][j] += a3*b;
            }
        }
        __syncthreads();
    }
#pragma unroll
    for (int i = 0; i < 4; i++)
#pragma unroll
        for (int j = 0; j < 4; j++)
            g_init_edge[(size_t)(e0+ty*4+i)*ED + tx + 16*j] = c2[i][j];
}

// ---------------- node update: segment softmax + agg + MLP + LN -------------
__global__ __launch_bounds__(256,1) void k_node(
    const float* __restrict__ x, const float* __restrict__ nW1,
    const float* __restrict__ nb1,
    const float* __restrict__ lg, const float* __restrict__ lb)
{
    __shared__ float agg[16*260];
    __shared__ float Bs[32*160];

    const int n0 = blockIdx.x*16;
    const int tid = threadIdx.x, g = tid>>4, t = tid&15;
    const int n = n0 + g;
    const int beg = g_rowptr[n], end = g_rowptr[n+1];

    float m = -1e30f;
    for (int i = beg+t; i < end; i += 16) m = fmaxf(m, g_logit[g_eids[i]]);
#pragma unroll
    for (int off = 8; off >= 1; off >>= 1) m = fmaxf(m, __shfl_xor_sync(0xffffffffu, m, off, 16));

    float den = 0.f;
    for (int i = beg+t; i < end; i += 16) den += expf(g_logit[g_eids[i]] - m);
#pragma unroll
    for (int off = 8; off >= 1; off >>= 1) den += __shfl_xor_sync(0xffffffffu, den, off, 16);
    den += 1e-16f;
    float inv_den = 1.f/den;

    float acc[16];
#pragma unroll
    for (int q = 0; q < 16; q++) acc[q] = 0.f;
    for (int i = beg; i < end; i++){
        int e = g_eids[i];
        float w = expf(g_logit[e] - m) * inv_den;
        const float* mr = g_msg + (size_t)e*HD;
#pragma unroll
        for (int q = 0; q < 16; q++) acc[q] += w * mr[t + 16*q];
    }
#pragma unroll
    for (int q = 0; q < 16; q++) agg[g*260 + t + 16*q] = acc[q];
    __syncthreads();

    float c[10];
#pragma unroll
    for (int j = 0; j < 10; j++) c[j] = 0.f;
    for (int kc = 0; kc < 256; kc += 32){
        for (int t2 = tid; t2 < 5120; t2 += 256){
            int kk = t2/160, nn = t2 - kk*160;
            Bs[t2] = nW1[(kc+kk)*ND + nn];
        }
        __syncthreads();
#pragma unroll 4
        for (int kk = 0; kk < 32; kk++){
            float a = agg[g*260 + kc+kk];
#pragma unroll
            for (int j = 0; j < 10; j++) c[j] += a * Bs[kk*160 + t + 16*j];
        }
        __syncthreads();
    }

    float rv[10], s = 0.f, s2 = 0.f;
#pragma unroll
    for (int j = 0; j < 10; j++){
        int cc = t + 16*j;
        float v = x[n*ND + cc] + c[j] + nb1[cc];
        rv[j] = v; s += v; s2 += v*v;
    }
#pragma unroll
    for (int off = 8; off >= 1; off >>= 1){
        s  += __shfl_xor_sync(0xffffffffu, s,  off, 16);
        s2 += __shfl_xor_sync(0xffffffffu, s2, off, 16);
    }
    float mu  = s * (1.f/ND);
    float var = s2 * (1.f/ND) - mu*mu;
    float inv = rsqrtf(var + 1e-5f);
#pragma unroll
    for (int j = 0; j < 10; j++){
        int cc = t + 16*j;
        g_node_lat[n*ND + cc] = (rv[j] - mu)*inv*lg[cc] + lb[cc];
    }
}

// ---------------- edge LN: edge_lat = LN(init_edge + new_edge) --------------
__global__ void k_edge_ln(const float* __restrict__ lg, const float* __restrict__ lb){
    int w = (blockIdx.x*blockDim.x + threadIdx.x) >> 5;
    int lane = threadIdx.x & 31;
    if (w >= NE) return;
    const float* a  = g_init_edge + (size_t)w*ED;
    const float* ne = g_new_edge  + (size_t)w*ED;
    float v0 = a[lane]    + ne[lane];
    float v1 = a[lane+32] + ne[lane+32];
    float s  = v0 + v1, s2 = v0*v0 + v1*v1;
#pragma unroll
    for (int off = 16; off >= 1; off >>= 1){
        s  += __shfl_xor_sync(0xffffffffu, s,  off);
        s2 += __shfl_xor_sync(0xffffffffu, s2, off);
    }
    float mu  = s * (1.f/ED);
    float var = s2 * (1.f/ED) - mu*mu;
    float inv = rsqrtf(var + 1e-5f);
    g_edge_lat[(size_t)w*ED + lane]    = (v0 - mu)*inv*lg[lane]    + lb[lane];
    g_edge_lat[(size_t)w*ED + lane+32] = (v1 - mu)*inv*lg[lane+32] + lb[lane+32];
}

// ---------------- launch -----------------------------------------------------
extern "C" void kernel_launch(void* const* d_in, const int* in_sizes, int n_in,
                              void* d_out, int out_size)
{
    const float* x     = (const float*)d_in[0];
    const float* ea    = (const float*)d_in[1];
    const float* encW1 = (const float*)d_in[2];
    const float* encb1 = (const float*)d_in[3];
    const float* encW2 = (const float*)d_in[4];
    const float* encb2 = (const float*)d_in[5];
    const float* eW1   = (const float*)d_in[6];
    const float* eb1   = (const float*)d_in[7];
    const float* eW2   = (const float*)d_in[8];
    const float* eb2   = (const float*)d_in[9];
    const float* mW1   = (const float*)d_in[10];
    const float* mb1   = (const float*)d_in[11];
    const float* attv  = (const float*)d_in[12];
    const float* nW1   = (const float*)d_in[13];
    const float* nb1   = (const float*)d_in[14];
    const float* ln_ng = (const float*)d_in[15];
    const float* ln_nb = (const float*)d_in[16];
    const float* ln_eg = (const float*)d_in[17];
    const float* ln_eb = (const float*)d_in[18];
    const int*   erow  = (const int*)d_in[19];
    const int*   ecol  = (const int*)d_in[20];

    void *p_deg, *p_rowptr, *p_fill, *p_node, *p_edge, *p_init, *p_P, *p_Pbase, *p_Penc;
    void *p_WEh, *p_WEl, *p_WPh, *p_WPl;
    cudaGetSymbolAddress(&p_deg,    g_deg);
    cudaGetSymbolAddress(&p_rowptr, g_rowptr);
    cudaGetSymbolAddress(&p_fill,   g_fill);
    cudaGetSymbolAddress(&p_node,   g_node_lat);
    cudaGetSymbolAddress(&p_edge,   g_edge_lat);
    cudaGetSymbolAddress(&p_init,   g_init_edge);
    cudaGetSymbolAddress(&p_P,      g_P);
    cudaGetSymbolAddress(&p_Pbase,  g_Pbase);
    cudaGetSymbolAddress(&p_Penc,   g_Penc);
    cudaGetSymbolAddress(&p_WEh,    gWEh);
    cudaGetSymbolAddress(&p_WEl,    gWEl);
    cudaGetSymbolAddress(&p_WPh,    gWPh);
    cudaGetSymbolAddress(&p_WPl,    gWPl);

    cudaFuncSetAttribute(k_edge_tc, cudaFuncAttributeMaxDynamicSharedMemorySize, 208896);

    // pack weight tables
    k_prep<<<480, 256>>>(eW1, mW1, encW1, eW2);

    // Pbase = x @ W_x (iteration-invariant half of P)
    {
        dim3 g((NN+127)/128, 6);
        k_gemm_bf<<<g, 256>>>(x, x, (const uint32_t*)p_WPh, (const uint32_t*)p_WPl,
                              160, 160, (float*)p_Pbase, 768, nullptr);
    }

    // CSR build
    cudaMemsetAsync(p_deg, 0, NN*sizeof(int), 0);
    k_hist<<<(NE+255)/256, 256>>>(erow);
    k_scan1<<<49, 256>>>();
    k_scan2<<<1, 32>>>();
    k_scan3<<<(NN+255)/256, 256>>>();
    cudaMemcpyAsync(p_fill, p_rowptr, NN*sizeof(int), cudaMemcpyDeviceToDevice, 0);
    k_scatter<<<(NE+255)/256, 256>>>(erow);

    // encoder: node-side bf16 GEMM + per-edge tail
    {
        dim3 g((NN+127)/128, 2);
        k_gemm_bf<<<g, 256>>>(x, x, (const uint32_t*)p_WEh, (const uint32_t*)p_WEl,
                              160, 80, (float*)p_Penc, 256, nullptr);
    }
    k_enc_edge<<<NE/64, 256>>>(ea, erow, ecol, encW1, encb1, encW2, encb2);

    cudaMemcpyAsync(p_node, x,      (size_t)NN*ND*sizeof(float), cudaMemcpyDeviceToDevice, 0);
    cudaMemcpyAsync(p_edge, p_init, (size_t)NE*ED*sizeof(float), cudaMemcpyDeviceToDevice, 0);

    for (int it = 0; it < 3; it++){
        dim3 g((NN+127)/128, 6);
        k_gemm_bf<<<g, 256>>>((const float*)p_node, (const float*)p_node,
                              (const uint32_t*)p_WPh + 80, (const uint32_t*)p_WPl + 80,
                              160, 160, (float*)p_P, 768, (const float*)p_Pbase);
        k_edge_tc<<<(NE+127)/128, 512, 208896>>>(erow, ecol, eb1, eb2, mb1, attv);
        k_node<<<NN/16, 256>>>(x, nW1, nb1, ln_ng, ln_nb);
        k_edge_ln<<<NE/8, 256>>>(ln_eg, ln_eb);
    }

    float* out = (float*)d_out;
    if (out_size >= NN*ND + NE*ED){
        cudaMemcpyAsync(out,         p_node, (size_t)NN*ND*sizeof(float), cudaMemcpyDeviceToDevice, 0);
        cudaMemcpyAsync(out + NN*ND, p_edge, (size_t)NE*ED*sizeof(float), cudaMemcpyDeviceToDevice, 0);
    } else if (out_size == NN*ND){
        cudaMemcpyAsync(out, p_node, (size_t)NN*ND*sizeof(float), cudaMemcpyDeviceToDevice, 0);
    } else {
        size_t nel = (size_t)((out_size < NE*ED) ? out_size : NE*ED);
        cudaMemcpyAsync(out, p_edge, nel*sizeof(float), cudaMemcpyDeviceToDevice, 0);
    }
}

// round 10
// speedup vs baseline: 1.0149x; 1.0149x over previous
#include <cuda_runtime.h>
#include <cuda_bf16.h>
#include <math.h>
#include <stdint.h>

#define NN 50000
#define NE 200000
#define ND 160
#define ED 64
#define RD 8
#define HD 256
#define EH 128

// ---------------- scratch (device globals; no runtime allocation) ----------
__device__ float g_init_edge[NE*ED];
__device__ float g_edge_lat [NE*ED];
__device__ float g_node_lat [NN*ND];
__device__ float g_msg      [NE*HD];
__device__ float g_logit    [NE];
__device__ float g_P        [(size_t)NN*768];   // [P1|P2|P3] per node
__device__ float g_Pbase    [(size_t)NN*768];   // x-part of P (iteration-invariant)
__device__ float g_Penc     [(size_t)NN*256];   // [enc1|enc2] per node
// packed bf16 hi/lo weight tables (u32 = 2 bf16 along K), K-major [n][k/2]
__device__ uint32_t gWPh[768*160], gWPl[768*160];
__device__ uint32_t gWEh[256*80],  gWEl[256*80];
__device__ uint32_t gB1h[256*64],  gB1l[256*64];
__device__ uint32_t gB2h[64*128],  gB2l[64*128];
__device__ uint32_t gB3h[256*32],  gB3l[256*32];
__device__ int   g_deg      [NN];
__device__ int   g_rowptr   [NN+1];
__device__ int   g_fill     [NN];
__device__ int   g_eids     [NE];
__device__ int   g_part     [64];

// ---------------- bf16 split helpers ----------------------------------------
__device__ __forceinline__ void split2(float x, float y, uint32_t& hi, uint32_t& lo){
    __nv_bfloat162 h = __floats2bfloat162_rn(x, y);
    hi = *(uint32_t*)&h;
    float rx = x - __bfloat162float(h.x);
    float ry = y - __bfloat162float(h.y);
    __nv_bfloat162 l = __floats2bfloat162_rn(rx, ry);
    lo = *(uint32_t*)&l;
}
__device__ __forceinline__ void mma_bf16(
    float& c0, float& c1, float& c2, float& c3,
    uint32_t a0, uint32_t a1, uint32_t a2, uint32_t a3, uint32_t b0, uint32_t b1)
{
    asm volatile(
        "mma.sync.aligned.m16n8k16.row.col.f32.bf16.bf16.f32 "
        "{%0,%1,%2,%3}, {%4,%5,%6,%7}, {%8,%9}, {%0,%1,%2,%3};"
        : "+f"(c0), "+f"(c1), "+f"(c2), "+f"(c3)
        : "r"(a0), "r"(a1), "r"(a2), "r"(a3), "r"(b0), "r"(b1));
}

// ---------------- CSR build --------------------------------------------------
__global__ void k_hist(const int* __restrict__ row){
    int e = blockIdx.x*blockDim.x + threadIdx.x;
    if (e < NE) atomicAdd(&g_deg[row[e]], 1);
}

__global__ void k_scan1(){
    __shared__ int ss[256];
    int b = blockIdx.x, base = b*1024, tid = threadIdx.x;
    int v[4], tsum = 0;
#pragma unroll
    for (int r = 0; r < 4; r++){
        int idx = base + tid*4 + r;
        v[r] = (idx < NN) ? g_deg[idx] : 0;
        tsum += v[r];
    }
    ss[tid] = tsum; __syncthreads();
    for (int off = 1; off < 256; off <<= 1){
        int add = (tid >= off) ? ss[tid-off] : 0;
        __syncthreads();
        ss[tid] += add;
        __syncthreads();
    }
    int run = ss[tid] - tsum;
#pragma unroll
    for (int r = 0; r < 4; r++){
        int idx = base + tid*4 + r;
        if (idx < NN) g_rowptr[idx] = run;
        run += v[r];
    }
    if (tid == 255) g_part[b] = ss[255];
}

__global__ void k_scan2(){
    if (threadIdx.x == 0){
        int run = 0;
        for (int i = 0; i < 49; i++){ int t = g_part[i]; g_part[i] = run; run += t; }
    }
}

__global__ void k_scan3(){
    int i = blockIdx.x*blockDim.x + threadIdx.x;
    if (i < NN) g_rowptr[i] += g_part[i >> 10];
    if (i == 0) g_rowptr[NN] = NE;
}

__global__ void k_scatter(const int* __restrict__ row){
    int e = blockIdx.x*blockDim.x + threadIdx.x;
    if (e < NE){
        int p = atomicAdd(&g_fill[row[e]], 1);
        g_eids[p] = e;
    }
}

// ---------------- pack all weight tables (bf16 hi/lo, K-major) ---------------
__global__ void k_prep(const float* __restrict__ eW1, const float* __restrict__ mW1,
                       const float* __restrict__ encW1, const float* __restrict__ eW2)
{
    int i = blockIdx.x*blockDim.x + threadIdx.x;
    if (i < 768*160){
        int n = i/160, w = i - n*160, k = w*2;
        float f0, f1;
        if (n < 256){ f0 = eW1[k*256+n]; f1 = eW1[(k+1)*256+n]; }
        else if (n < 512){ int nn = n-256; f0 = eW1[(320+k)*256+nn]; f1 = eW1[(321+k)*256+nn]; }
        else { int nn = n-512; f0 = mW1[k*256+nn]; f1 = mW1[(k+1)*256+nn]; }
        split2(f0, f1, gWPh[i], gWPl[i]);
    }
    if (i < 256*80){
        int n = i/80, w = i - n*80, k = w*2;
        float f0, f1;
        if (n < 128){ f0 = encW1[k*128+n]; f1 = encW1[(k+1)*128+n]; }
        else { int nn = n-128; f0 = encW1[(160+k)*128+nn]; f1 = encW1[(161+k)*128+nn]; }
        split2(f0, f1, gWEh[i], gWEl[i]);
    }
    if (i < 256*64){
        int n = i/64, w = i - n*64, k = w*2;
        split2(eW1[(640+k)*256+n], eW1[(641+k)*256+n], gB1h[i], gB1l[i]);
    }
    if (i < 64*128){
        int n = i/128, w = i - n*128, k = w*2;
        split2(eW2[k*64+n], eW2[(k+1)*64+n], gB2h[i], gB2l[i]);
    }
    if (i < 256*32){
        int n = i/32, w = i - n*32, k = w*2;
        split2(mW1[(320+k)*256+n], mW1[(321+k)*256+n], gB3h[i], gB3l[i]);
    }
}

// ---------------- bf16 3-split dense GEMM (m16n8k16) -------------------------
__global__ __launch_bounds__(256,2) void k_gemm_bf(
    const float* __restrict__ A0, const float* __restrict__ A1,
    const uint32_t* __restrict__ Bh, const uint32_t* __restrict__ Bl,
    int K, int bstrW,
    float* __restrict__ out, int ostride, const float* __restrict__ base)
{
    __shared__ uint32_t sAh[128*20], sAl[128*20], sBh[128*20], sBl[128*20];
    const int tid = threadIdx.x, wid = tid>>5, lane = tid&31;
    const int gid = lane>>2, tq = lane&3;
    const int warp_m = (wid & 1)*64, warp_n = (wid >> 1)*32;
    const int m0 = blockIdx.x*128, n0 = blockIdx.y*128;

    float c[4][4][4];
#pragma unroll
    for (int i = 0; i < 4; i++)
#pragma unroll
        for (int j = 0; j < 4; j++)
#pragma unroll
            for (int r = 0; r < 4; r++) c[i][j][r] = 0.f;

    const int nk = K >> 5;
    for (int ch = 0; ch < nk; ch++){
        const int kc = ch*32;
        const float* A = (kc < 160) ? A0 : A1;
        const int ac = (kc < 160) ? kc : (kc - 160);
#pragma unroll
        for (int p = 0; p < 4; p++){
            int lin = tid + p*256;
            int row = lin>>3, f4 = lin&7;
            int gm = m0 + row;
            float4 v = make_float4(0.f,0.f,0.f,0.f);
            if (gm < NN) v = *(const float4*)&A[(size_t)gm*ND + ac + f4*4];
            uint32_t h0,l0,h1,l1;
            split2(v.x, v.y, h0, l0);
            split2(v.z, v.w, h1, l1);
            sAh[row*20 + f4*2]   = h0; sAh[row*20 + f4*2+1] = h1;
            sAl[row*20 + f4*2]   = l0; sAl[row*20 + f4*2+1] = l1;
        }
#pragma unroll
        for (int p = 0; p < 2; p++){
            int lin = tid + p*256;
            int row = lin>>2, q = lin&3;
            size_t gofs = (size_t)(n0+row)*bstrW + (kc>>1) + q*4;
            *(uint4*)&sBh[row*20 + q*4] = *(const uint4*)&Bh[gofs];
            *(uint4*)&sBl[row*20 + q*4] = *(const uint4*)&Bl[gofs];
        }
        __syncthreads();
#pragma unroll
        for (int s = 0; s < 2; s++){
            const int kb = s*8 + tq;
            uint32_t bh0[4], bh1[4], bl0[4], bl1[4];
#pragma unroll
            for (int nt = 0; nt < 4; nt++){
                int nr = warp_n + nt*8 + gid;
                bh0[nt] = sBh[nr*20 + kb]; bh1[nt] = sBh[nr*20 + kb + 4];
                bl0[nt] = sBl[nr*20 + kb]; bl1[nt] = sBl[nr*20 + kb + 4];
            }
#pragma unroll
            for (int mt = 0; mt < 4; mt++){
                int ar = warp_m + mt*16 + gid;
                uint32_t ah0 = sAh[ar*20+kb],     ah1 = sAh[(ar+8)*20+kb];
                uint32_t ah2 = sAh[ar*20+kb+4],   ah3 = sAh[(ar+8)*20+kb+4];
                uint32_t al0 = sAl[ar*20+kb],     al1 = sAl[(ar+8)*20+kb];
                uint32_t al2 = sAl[ar*20+kb+4],   al3 = sAl[(ar+8)*20+kb+4];
#pragma unroll
                for (int nt = 0; nt < 4; nt++){
                    mma_bf16(c[mt][nt][0], c[mt][nt][1], c[mt][nt][2], c[mt][nt][3],
                             ah0, ah1, ah2, ah3, bh0[nt], bh1[nt]);
                    mma_bf16(c[mt][nt][0], c[mt][nt][1], c[mt][nt][2], c[mt][nt][3],
                             ah0, ah1, ah2, ah3, bl0[nt], bl1[nt]);
                    mma_bf16(c[mt][nt][0], c[mt][nt][1], c[mt][nt][2], c[mt][nt][3],
                             al0, al1, al2, al3, bh0[nt], bh1[nt]);
                }
            }
        }
        __syncthreads();
    }

#pragma unroll
    for (int mt = 0; mt < 4; mt++){
        int r0 = m0 + warp_m + mt*16 + gid;
        int r1 = r0 + 8;
#pragma unroll
        for (int nt = 0; nt < 4; nt++){
            int gn = n0 + warp_n + nt*8 + tq*2;
            if (r0 < NN){
                float2 v = make_float2(c[mt][nt][0], c[mt][nt][1]);
                if (base){ float2 b = *(const float2*)&base[(size_t)r0*ostride + gn]; v.x += b.x; v.y += b.y; }
                *(float2*)&out[(size_t)r0*ostride + gn] = v;
            }
            if (r1 < NN){
                float2 v = make_float2(c[mt][nt][2], c[mt][nt][3]);
                if (base){ float2 b = *(const float2*)&base[(size_t)r1*ostride + gn]; v.x += b.x; v.y += b.y; }
                *(float2*)&out[(size_t)r1*ostride + gn] = v;
            }
        }
    }
}

// ---------------- fused edge kernel (round-7 base + fused edge LN) -----------
// 128 edges/block, 512 threads. B3 now stride 36, full-K (round-8-proven).
__global__ __launch_bounds__(512,1) void k_edge_tc(
    const int* __restrict__ row, const int* __restrict__ col,
    const float* __restrict__ eb1, const float* __restrict__ eb2,
    const float* __restrict__ mb1, const float* __restrict__ attv,
    const float* __restrict__ lgE, const float* __restrict__ lbE)
{
    extern __shared__ uint32_t esm[];
    uint32_t* Ah  = esm;              // [128][68]
    uint32_t* Al  = esm + 8704;
    uint32_t* B1h = esm + 17408;      // [256][20]
    uint32_t* B1l = esm + 22528;
    uint32_t* Hh  = esm;              // [128][132] overlay (phase2)
    uint32_t* Hl  = esm + 16896;
    uint32_t* B2h = esm + 33792;      // [64][36]
    uint32_t* B2l = esm + 36096;
    uint32_t* NEh = esm;              // [128][36] overlay (after phase2)
    uint32_t* NEl = esm + 4608;
    uint32_t* B3h = esm + 9216;       // [256][36] full-K (stride 36!)
    uint32_t* B3l = esm + 18432;
    __shared__ int sR[128], sC[128];
    __shared__ float sAtt[256];
    __shared__ float sLog[128];
    __shared__ float sSum[128], sSq[128], sMu[128], sInv[128];

    const int tid = threadIdx.x, wid = tid>>5, lane = tid&31;
    const int gid = lane>>2, tq = lane&3;
    const int warp_m  = (wid & 1)*64;
    const int warp_n  = (wid >> 1)*32;
    const int warp_n2 = (wid >> 1)*8;
    const int e0 = blockIdx.x*128;

    if (tid < 128){
        int ge = e0 + tid;
        sR[tid] = (ge < NE) ? row[ge] : 0;
        sC[tid] = (ge < NE) ? col[ge] : 0;
        sLog[tid] = 0.f; sSum[tid] = 0.f; sSq[tid] = 0.f;
    }
    if (tid < 256) sAtt[tid] = attv[tid];
    __syncthreads();

    // ---- phase 1: stage A + C init from P gathers ---------------------------
    for (int lin = tid; lin < 8192; lin += 512){
        int r = lin>>6, w = lin&63, k = w*2;
        float2 v = make_float2(0.f, 0.f);
        if (e0 + r < NE)
            v = (k < 64) ? *(const float2*)&g_init_edge[(size_t)(e0+r)*ED + k]
                         : *(const float2*)&g_edge_lat [(size_t)(e0+r)*ED + (k-64)];
        split2(v.x, v.y, Ah[r*68+w], Al[r*68+w]);
    }
    float c1[4][4][4];
#pragma unroll
    for (int mt = 0; mt < 4; mt++){
        int rA = warp_m + mt*16 + gid, rB = rA + 8;
        size_t prA = (size_t)sR[rA]*768, pcA = (size_t)sC[rA]*768;
        size_t prB = (size_t)sR[rB]*768, pcB = (size_t)sC[rB]*768;
#pragma unroll
        for (int nt = 0; nt < 4; nt++){
            int cn = warp_n + nt*8 + tq*2;
            float2 b  = *(const float2*)&eb1[cn];
            float2 a1 = *(const float2*)&g_P[prA + cn];
            float2 a2 = *(const float2*)&g_P[pcA + 256 + cn];
            float2 a3 = *(const float2*)&g_P[prB + cn];
            float2 a4 = *(const float2*)&g_P[pcB + 256 + cn];
            c1[mt][nt][0] = a1.x + a2.x + b.x;
            c1[mt][nt][1] = a1.y + a2.y + b.y;
            c1[mt][nt][2] = a3.x + a4.x + b.x;
            c1[mt][nt][3] = a3.y + a4.y + b.y;
        }
    }
    __syncthreads();

#pragma unroll
    for (int ch = 0; ch < 4; ch++){
        for (int lin = tid; lin < 1024; lin += 512){
            int r = lin>>2, q = lin&3;
            size_t gofs = (size_t)r*64 + ch*16 + q*4;
            *(uint4*)&B1h[r*20 + q*4] = *(const uint4*)&gB1h[gofs];
            *(uint4*)&B1l[r*20 + q*4] = *(const uint4*)&gB1l[gofs];
        }
        __syncthreads();
#pragma unroll
        for (int s = 0; s < 2; s++){
            int kb = s*8 + tq, ka = ch*16 + kb;
            uint32_t bh0[4], bh1[4], bl0[4], bl1[4];
#pragma unroll
            for (int nt = 0; nt < 4; nt++){
                int nr = warp_n + nt*8 + gid;
                bh0[nt] = B1h[nr*20+kb]; bh1[nt] = B1h[nr*20+kb+4];
                bl0[nt] = B1l[nr*20+kb]; bl1[nt] = B1l[nr*20+kb+4];
            }
#pragma unroll
            for (int mt = 0; mt < 4; mt++){
                int ar = warp_m + mt*16 + gid;
                uint32_t ah0 = Ah[ar*68+ka],   ah1 = Ah[(ar+8)*68+ka];
                uint32_t ah2 = Ah[ar*68+ka+4], ah3 = Ah[(ar+8)*68+ka+4];
                uint32_t al0 = Al[ar*68+ka],   al1 = Al[(ar+8)*68+ka];
                uint32_t al2 = Al[ar*68+ka+4], al3 = Al[(ar+8)*68+ka+4];
#pragma unroll
                for (int nt = 0; nt < 4; nt++){
                    mma_bf16(c1[mt][nt][0],c1[mt][nt][1],c1[mt][nt][2],c1[mt][nt][3],
                             ah0,ah1,ah2,ah3, bh0[nt],bh1[nt]);
                    mma_bf16(c1[mt][nt][0],c1[mt][nt][1],c1[mt][nt][2],c1[mt][nt][3],
                             ah0,ah1,ah2,ah3, bl0[nt],bl1[nt]);
                    mma_bf16(c1[mt][nt][0],c1[mt][nt][1],c1[mt][nt][2],c1[mt][nt][3],
                             al0,al1,al2,al3, bh0[nt],bh1[nt]);
                }
            }
        }
        __syncthreads();
    }

    // write hidden (relu, bf16 split) over A/B1 region
#pragma unroll
    for (int mt = 0; mt < 4; mt++){
        int rA = warp_m + mt*16 + gid, rB = rA + 8;
#pragma unroll
        for (int nt = 0; nt < 4; nt++){
            int wcol = (warp_n>>1) + nt*4 + tq;
            float v0 = fmaxf(c1[mt][nt][0], 0.f), v1 = fmaxf(c1[mt][nt][1], 0.f);
            float v2 = fmaxf(c1[mt][nt][2], 0.f), v3 = fmaxf(c1[mt][nt][3], 0.f);
            split2(v0, v1, Hh[rA*132+wcol], Hl[rA*132+wcol]);
            split2(v2, v3, Hh[rB*132+wcol], Hl[rB*132+wcol]);
        }
    }
    __syncthreads();

    // ---- phase 2 ------------------------------------------------------------
    float c2[4][4];
#pragma unroll
    for (int mt = 0; mt < 4; mt++){
        float2 b = *(const float2*)&eb2[warp_n2 + tq*2];
        c2[mt][0] = b.x; c2[mt][1] = b.y; c2[mt][2] = b.x; c2[mt][3] = b.y;
    }
#pragma unroll
    for (int ch = 0; ch < 4; ch++){
        {
            int r = tid>>3, q = tid&7;
            size_t gofs = (size_t)r*128 + ch*32 + q*4;
            *(uint4*)&B2h[r*36 + q*4] = *(const uint4*)&gB2h[gofs];
            *(uint4*)&B2l[r*36 + q*4] = *(const uint4*)&gB2l[gofs];
        }
        __syncthreads();
#pragma unroll
        for (int s = 0; s < 4; s++){
            int kb = s*8 + tq, ka = ch*32 + kb;
            int nr = warp_n2 + gid;
            uint32_t bh0 = B2h[nr*36+kb], bh1 = B2h[nr*36+kb+4];
            uint32_t bl0 = B2l[nr*36+kb], bl1 = B2l[nr*36+kb+4];
#pragma unroll
            for (int mt = 0; mt < 4; mt++){
                int ar = warp_m + mt*16 + gid;
                uint32_t ah0 = Hh[ar*132+ka],   ah1 = Hh[(ar+8)*132+ka];
                uint32_t ah2 = Hh[ar*132+ka+4], ah3 = Hh[(ar+8)*132+ka+4];
                uint32_t al0 = Hl[ar*132+ka],   al1 = Hl[(ar+8)*132+ka];
                uint32_t al2 = Hl[ar*132+ka+4], al3 = Hl[(ar+8)*132+ka+4];
                mma_bf16(c2[mt][0],c2[mt][1],c2[mt][2],c2[mt][3], ah0,ah1,ah2,ah3, bh0,bh1);
                mma_bf16(c2[mt][0],c2[mt][1],c2[mt][2],c2[mt][3], ah0,ah1,ah2,ah3, bl0,bl1);
                mma_bf16(c2[mt][0],c2[mt][1],c2[mt][2],c2[mt][3], al0,al1,al2,al3, bh0,bh1);
            }
        }
        __syncthreads();
    }

    // ---- NE pack (new_edge) + LN stats; stage full B3 (stride 36) ----------
#pragma unroll
    for (int mt = 0; mt < 4; mt++){
        int rA = warp_m + mt*16 + gid, rB = rA + 8;
        int cn = warp_n2 + tq*2;
        int wcol = (warp_n2>>1) + tq;
        split2(c2[mt][0], c2[mt][1], NEh[rA*36+wcol], NEl[rA*36+wcol]);
        split2(c2[mt][2], c2[mt][3], NEh[rB*36+wcol], NEl[rB*36+wcol]);
        float2 iA = make_float2(0.f,0.f), iB = make_float2(0.f,0.f);
        if (e0 + rA < NE) iA = *(const float2*)&g_init_edge[(size_t)(e0+rA)*ED + cn];
        if (e0 + rB < NE) iB = *(const float2*)&g_init_edge[(size_t)(e0+rB)*ED + cn];
        c2[mt][0] += iA.x; c2[mt][1] += iA.y;     // c2 now holds t = init + new
        c2[mt][2] += iB.x; c2[mt][3] += iB.y;
        atomicAdd(&sSum[rA], c2[mt][0] + c2[mt][1]);
        atomicAdd(&sSq [rA], c2[mt][0]*c2[mt][0] + c2[mt][1]*c2[mt][1]);
        atomicAdd(&sSum[rB], c2[mt][2] + c2[mt][3]);
        atomicAdd(&sSq [rB], c2[mt][2]*c2[mt][2] + c2[mt][3]*c2[mt][3]);
    }
    for (int lin = tid; lin < 2048; lin += 512){
        int r = lin>>3, q = lin&7;
        size_t gofs = (size_t)r*32 + q*4;
        *(uint4*)&B3h[r*36 + q*4] = *(const uint4*)&gB3h[gofs];
        *(uint4*)&B3l[r*36 + q*4] = *(const uint4*)&gB3l[gofs];
    }
    // phase3 accumulator init from P gathers (no smem dep)
    float c3[4][4][4];
#pragma unroll
    for (int mt = 0; mt < 4; mt++){
        int rA = warp_m + mt*16 + gid, rB = rA + 8;
        size_t pcA = (size_t)sC[rA]*768, pcB = (size_t)sC[rB]*768;
#pragma unroll
        for (int nt = 0; nt < 4; nt++){
            int cn = warp_n + nt*8 + tq*2;
            float2 b  = *(const float2*)&mb1[cn];
            float2 a1 = *(const float2*)&g_P[pcA + 512 + cn];
            float2 a2 = *(const float2*)&g_P[pcB + 512 + cn];
            c3[mt][nt][0] = a1.x + b.x; c3[mt][nt][1] = a1.y + b.y;
            c3[mt][nt][2] = a2.x + b.x; c3[mt][nt][3] = a2.y + b.y;
        }
    }
    __syncthreads();

    if (tid < 128){
        float mu = sSum[tid] * (1.f/ED);
        float var = sSq[tid] * (1.f/ED) - mu*mu;
        sMu[tid] = mu;
        sInv[tid] = rsqrtf(var + 1e-5f);
    }
    __syncthreads();

    // write edge_lat = (t - mu)*inv*lg + lb
#pragma unroll
    for (int mt = 0; mt < 4; mt++){
        int rA = warp_m + mt*16 + gid, rB = rA + 8;
        int cn = warp_n2 + tq*2;
        float g0 = lgE[cn], g1 = lgE[cn+1], b0 = lbE[cn], b1 = lbE[cn+1];
        if (e0 + rA < NE){
            float mu = sMu[rA], inv = sInv[rA];
            *(float2*)&g_edge_lat[(size_t)(e0+rA)*ED + cn] =
                make_float2((c2[mt][0]-mu)*inv*g0 + b0, (c2[mt][1]-mu)*inv*g1 + b1);
        }
        if (e0 + rB < NE){
            float mu = sMu[rB], inv = sInv[rB];
            *(float2*)&g_edge_lat[(size_t)(e0+rB)*ED + cn] =
                make_float2((c2[mt][2]-mu)*inv*g0 + b0, (c2[mt][3]-mu)*inv*g1 + b1);
        }
    }

    // ---- phase 3 MMA loop (B3 stride 36) ------------------------------------
#pragma unroll
    for (int s = 0; s < 4; s++){
        int ka = s*8 + tq;
        uint32_t bh0[4], bh1[4], bl0[4], bl1[4];
#pragma unroll
        for (int nt = 0; nt < 4; nt++){
            int nr = warp_n + nt*8 + gid;
            bh0[nt] = B3h[nr*36+ka]; bh1[nt] = B3h[nr*36+ka+4];
            bl0[nt] = B3l[nr*36+ka]; bl1[nt] = B3l[nr*36+ka+4];
        }
#pragma unroll
        for (int mt = 0; mt < 4; mt++){
            int ar = warp_m + mt*16 + gid;
            uint32_t ah0 = NEh[ar*36+ka],   ah1 = NEh[(ar+8)*36+ka];
            uint32_t ah2 = NEh[ar*36+ka+4], ah3 = NEh[(ar+8)*36+ka+4];
            uint32_t al0 = NEl[ar*36+ka],   al1 = NEl[(ar+8)*36+ka];
            uint32_t al2 = NEl[ar*36+ka+4], al3 = NEl[(ar+8)*36+ka+4];
#pragma unroll
            for (int nt = 0; nt < 4; nt++){
                mma_bf16(c3[mt][nt][0],c3[mt][nt][1],c3[mt][nt][2],c3[mt][nt][3],
                         ah0,ah1,ah2,ah3, bh0[nt],bh1[nt]);
                mma_bf16(c3[mt][nt][0],c3[mt][nt][1],c3[mt][nt][2],c3[mt][nt][3],
                         ah0,ah1,ah2,ah3, bl0[nt],bl1[nt]);
                mma_bf16(c3[mt][nt][0],c3[mt][nt][1],c3[mt][nt][2],c3[mt][nt][3],
                         al0,al1,al2,al3, bh0[nt],bh1[nt]);
            }
        }
    }

    // epilogue: relu -> g_msg, attention partial dot, logit
    float pa[4][2];
#pragma unroll
    for (int mt = 0; mt < 4; mt++){ pa[mt][0] = 0.f; pa[mt][1] = 0.f; }
#pragma unroll
    for (int mt = 0; mt < 4; mt++){
        int rA = warp_m + mt*16 + gid, rB = rA + 8;
#pragma unroll
        for (int nt = 0; nt < 4; nt++){
            int cn = warp_n + nt*8 + tq*2;
            float av0 = sAtt[cn], av1 = sAtt[cn+1];
            float v0 = fmaxf(c3[mt][nt][0], 0.f), v1 = fmaxf(c3[mt][nt][1], 0.f);
            float v2 = fmaxf(c3[mt][nt][2], 0.f), v3 = fmaxf(c3[mt][nt][3], 0.f);
            if (e0 + rA < NE)
                *(float2*)&g_msg[(size_t)(e0+rA)*HD + cn] = make_float2(v0, v1);
            if (e0 + rB < NE)
                *(float2*)&g_msg[(size_t)(e0+rB)*HD + cn] = make_float2(v2, v3);
            pa[mt][0] += v0*av0 + v1*av1;
            pa[mt][1] += v2*av0 + v3*av1;
        }
    }
#pragma unroll
    for (int off = 1; off <= 2; off <<= 1){
#pragma unroll
        for (int mt = 0; mt < 4; mt++){
            pa[mt][0] += __shfl_xor_sync(0xffffffffu, pa[mt][0], off, 4);
            pa[mt][1] += __shfl_xor_sync(0xffffffffu, pa[mt][1], off, 4);
        }
    }
    if (tq == 0){
#pragma unroll
        for (int mt = 0; mt < 4; mt++){
            atomicAdd(&sLog[warp_m + mt*16 + gid],     pa[mt][0]);
            atomicAdd(&sLog[warp_m + mt*16 + gid + 8], pa[mt][1]);
        }
    }
    __syncthreads();
    if (tid < 128 && e0 + tid < NE){
        float p = sLog[tid];
        g_logit[e0+tid] = (p > 0.f) ? p : 0.2f*p;
    }
}

// ---------------- edge encoder tail: per-edge part (FFMA, small) -------------
__global__ __launch_bounds__(256,2) void k_enc_edge(
    const float* __restrict__ ea,
    const int* __restrict__ row, const int* __restrict__ col,
    const float* __restrict__ encW1, const float* __restrict__ encb1,
    const float* __restrict__ encW2, const float* __restrict__ encb2)
{
    __shared__ float As[64*9];
    __shared__ float Bs[16*64];
    __shared__ float Hid[64*132];
    __shared__ int sR[64], sC[64];

    const int e0 = blockIdx.x*64;
    const int tid = threadIdx.x, ty = tid>>4, tx = tid&15;
    if (tid < 64){ sR[tid] = row[e0+tid]; sC[tid] = col[e0+tid]; }
    __syncthreads();

    float c[4][8];
#pragma unroll
    for (int i = 0; i < 4; i++){
        int r = ty*4+i;
#pragma unroll
        for (int j = 0; j < 8; j++){
            int n = tx + 16*j;
            c[i][j] = g_Penc[(size_t)sR[r]*256 + n]
                    + g_Penc[(size_t)sC[r]*256 + 128 + n]
                    + encb1[n];
        }
    }
    for (int t = tid; t < 512; t += 256){
        int el = t>>3, kk = t&7;
        As[el*9+kk] = ea[(e0+el)*RD + kk];
    }
    for (int t = tid; t < 1024; t += 256){
        int kk = t>>7, n = t&127;
        Bs[t] = encW1[(320+kk)*EH + n];
    }
    __syncthreads();
#pragma unroll
    for (int kk = 0; kk < 8; kk++){
        float a0 = As[(ty*4+0)*9+kk], a1 = As[(ty*4+1)*9+kk];
        float a2 = As[(ty*4+2)*9+kk], a3 = As[(ty*4+3)*9+kk];
#pragma unroll
        for (int j = 0; j < 8; j++){
            float b = Bs[kk*128 + tx + 16*j];
            c[0][j] += a0*b; c[1][j] += a1*b; c[2][j] += a2*b; c[3][j] += a3*b;
        }
    }
    __syncthreads();
#pragma unroll
    for (int i = 0; i < 4; i++)
#pragma unroll
        for (int j = 0; j < 8; j++){
            int n = tx + 16*j;
            Hid[(ty*4+i)*132 + n] = fmaxf(c[i][j], 0.f);
        }
    __syncthreads();

    float c2[4][4];
#pragma unroll
    for (int i = 0; i < 4; i++)
#pragma unroll
        for (int j = 0; j < 4; j++) c2[i][j] = encb2[tx+16*j];

    for (int kc = 0; kc < 128; kc += 16){
        for (int t = tid; t < 1024; t += 256){
            int kk = t>>6, n = t&63;
            Bs[t] = encW2[(kc+kk)*ED + n];
        }
        __syncthreads();
#pragma unroll
        for (int kk = 0; kk < 16; kk++){
            float a0 = Hid[(ty*4+0)*132 + kc+kk], a1 = Hid[(ty*4+1)*132 + kc+kk];
            float a2 = Hid[(ty*4+2)*132 + kc+kk], a3 = Hid[(ty*4+3)*132 + kc+kk];
#pragma unroll
            for (int j = 0; j < 4; j++){
                float b = Bs[kk*64 + tx + 16*j];
                c2[0][j] += a0*b; c2[1][j] += a1*b; c2[2][j] += a2*b; c2[3][j] += a3*b;
            }
        }
        __syncthreads();
    }
#pragma unroll
    for (int i = 0; i < 4; i++)
#pragma unroll
        for (int j = 0; j < 4; j++)
            g_init_edge[(size_t)(e0+ty*4+i)*ED + tx + 16*j] = c2[i][j];
}

// ---------------- node update: segment softmax + agg + MLP + LN -------------
__global__ __launch_bounds__(256,1) void k_node(
    const float* __restrict__ x, const float* __restrict__ nW1,
    const float* __restrict__ nb1,
    const float* __restrict__ lg, const float* __restrict__ lb)
{
    __shared__ float agg[16*260];
    __shared__ float Bs[32*160];

    const int n0 = blockIdx.x*16;
    const int tid = threadIdx.x, g = tid>>4, t = tid&15;
    const int n = n0 + g;
    const int beg = g_rowptr[n], end = g_rowptr[n+1];

    float m = -1e30f;
    for (int i = beg+t; i < end; i += 16) m = fmaxf(m, g_logit[g_eids[i]]);
#pragma unroll
    for (int off = 8; off >= 1; off >>= 1) m = fmaxf(m, __shfl_xor_sync(0xffffffffu, m, off, 16));

    float den = 0.f;
    for (int i = beg+t; i < end; i += 16) den += expf(g_logit[g_eids[i]] - m);
#pragma unroll
    for (int off = 8; off >= 1; off >>= 1) den += __shfl_xor_sync(0xffffffffu, den, off, 16);
    den += 1e-16f;
    float inv_den = 1.f/den;

    float acc[16];
#pragma unroll
    for (int q = 0; q < 16; q++) acc[q] = 0.f;
    for (int i = beg; i < end; i++){
        int e = g_eids[i];
        float w = expf(g_logit[e] - m) * inv_den;
        const float* mr = g_msg + (size_t)e*HD;
#pragma unroll
        for (int q = 0; q < 16; q++) acc[q] += w * mr[t + 16*q];
    }
#pragma unroll
    for (int q = 0; q < 16; q++) agg[g*260 + t + 16*q] = acc[q];
    __syncthreads();

    float c[10];
#pragma unroll
    for (int j = 0; j < 10; j++) c[j] = 0.f;
    for (int kc = 0; kc < 256; kc += 32){
        for (int t2 = tid; t2 < 5120; t2 += 256){
            int kk = t2/160, nn = t2 - kk*160;
            Bs[t2] = nW1[(kc+kk)*ND + nn];
        }
        __syncthreads();
#pragma unroll 4
        for (int kk = 0; kk < 32; kk++){
            float a = agg[g*260 + kc+kk];
#pragma unroll
            for (int j = 0; j < 10; j++) c[j] += a * Bs[kk*160 + t + 16*j];
        }
        __syncthreads();
    }

    float rv[10], s = 0.f, s2 = 0.f;
#pragma unroll
    for (int j = 0; j < 10; j++){
        int cc = t + 16*j;
        float v = x[n*ND + cc] + c[j] + nb1[cc];
        rv[j] = v; s += v; s2 += v*v;
    }
#pragma unroll
    for (int off = 8; off >= 1; off >>= 1){
        s  += __shfl_xor_sync(0xffffffffu, s,  off, 16);
        s2 += __shfl_xor_sync(0xffffffffu, s2, off, 16);
    }
    float mu  = s * (1.f/ND);
    float var = s2 * (1.f/ND) - mu*mu;
    float inv = rsqrtf(var + 1e-5f);
#pragma unroll
    for (int j = 0; j < 10; j++){
        int cc = t + 16*j;
        g_node_lat[n*ND + cc] = (rv[j] - mu)*inv*lg[cc] + lb[cc];
    }
}

// ---------------- launch -----------------------------------------------------
extern "C" void kernel_launch(void* const* d_in, const int* in_sizes, int n_in,
                              void* d_out, int out_size)
{
    const float* x     = (const float*)d_in[0];
    const float* ea    = (const float*)d_in[1];
    const float* encW1 = (const float*)d_in[2];
    const float* encb1 = (const float*)d_in[3];
    const float* encW2 = (const float*)d_in[4];
    const float* encb2 = (const float*)d_in[5];
    const float* eW1   = (const float*)d_in[6];
    const float* eb1   = (const float*)d_in[7];
    const float* eW2   = (const float*)d_in[8];
    const float* eb2   = (const float*)d_in[9];
    const float* mW1   = (const float*)d_in[10];
    const float* mb1   = (const float*)d_in[11];
    const float* attv  = (const float*)d_in[12];
    const float* nW1   = (const float*)d_in[13];
    const float* nb1   = (const float*)d_in[14];
    const float* ln_ng = (const float*)d_in[15];
    const float* ln_nb = (const float*)d_in[16];
    const float* ln_eg = (const float*)d_in[17];
    const float* ln_eb = (const float*)d_in[18];
    const int*   erow  = (const int*)d_in[19];
    const int*   ecol  = (const int*)d_in[20];

    void *p_deg, *p_rowptr, *p_fill, *p_node, *p_edge, *p_init, *p_P, *p_Pbase, *p_Penc;
    void *p_WEh, *p_WEl, *p_WPh, *p_WPl;
    cudaGetSymbolAddress(&p_deg,    g_deg);
    cudaGetSymbolAddress(&p_rowptr, g_rowptr);
    cudaGetSymbolAddress(&p_fill,   g_fill);
    cudaGetSymbolAddress(&p_node,   g_node_lat);
    cudaGetSymbolAddress(&p_edge,   g_edge_lat);
    cudaGetSymbolAddress(&p_init,   g_init_edge);
    cudaGetSymbolAddress(&p_P,      g_P);
    cudaGetSymbolAddress(&p_Pbase,  g_Pbase);
    cudaGetSymbolAddress(&p_Penc,   g_Penc);
    cudaGetSymbolAddress(&p_WEh,    gWEh);
    cudaGetSymbolAddress(&p_WEl,    gWEl);
    cudaGetSymbolAddress(&p_WPh,    gWPh);
    cudaGetSymbolAddress(&p_WPl,    gWPl);

    cudaFuncSetAttribute(k_edge_tc, cudaFuncAttributeMaxDynamicSharedMemorySize, 153600);

    // persistent side stream + events (created once; capture-legal fork/join)
    static cudaStream_t s1 = nullptr;
    static cudaEvent_t evA = nullptr, evB = nullptr;
    if (s1 == nullptr){
        cudaStreamCreateWithFlags(&s1, cudaStreamNonBlocking);
        cudaEventCreateWithFlags(&evA, cudaEventDisableTiming);
        cudaEventCreateWithFlags(&evB, cudaEventDisableTiming);
    }

    // fork: CSR build on s1, GEMM prologue on stream 0
    cudaEventRecord(evA, 0);
    cudaStreamWaitEvent(s1, evA, 0);

    cudaMemsetAsync(p_deg, 0, NN*sizeof(int), s1);
    k_hist<<<(NE+255)/256, 256, 0, s1>>>(erow);
    k_scan1<<<49, 256, 0, s1>>>();
    k_scan2<<<1, 32, 0, s1>>>();
    k_scan3<<<(NN+255)/256, 256, 0, s1>>>();
    cudaMemcpyAsync(p_fill, p_rowptr, NN*sizeof(int), cudaMemcpyDeviceToDevice, s1);
    k_scatter<<<(NE+255)/256, 256, 0, s1>>>(erow);

    // stream 0: weight pack -> GEMMs -> encoder tail -> copies
    k_prep<<<480, 256>>>(eW1, mW1, encW1, eW2);
    {
        dim3 g((NN+127)/128, 6);
        k_gemm_bf<<<g, 256>>>(x, x, (const uint32_t*)p_WPh, (const uint32_t*)p_WPl,
                              160, 160, (float*)p_Pbase, 768, nullptr);
    }
    {
        dim3 g((NN+127)/128, 2);
        k_gemm_bf<<<g, 256>>>(x, x, (const uint32_t*)p_WEh, (const uint32_t*)p_WEl,
                              160, 80, (float*)p_Penc, 256, nullptr);
    }
    k_enc_edge<<<NE/64, 256>>>(ea, erow, ecol, encW1, encb1, encW2, encb2);

    cudaMemcpyAsync(p_node, x,      (size_t)NN*ND*sizeof(float), cudaMemcpyDeviceToDevice, 0);
    cudaMemcpyAsync(p_edge, p_init, (size_t)NE*ED*sizeof(float), cudaMemcpyDeviceToDevice, 0);

    // join CSR before the iteration loop (k_node needs rowptr/eids)
    cudaEventRecord(evB, s1);
    cudaStreamWaitEvent(0, evB, 0);

    for (int it = 0; it < 3; it++){
        dim3 g((NN+127)/128, 6);
        k_gemm_bf<<<g, 256>>>((const float*)p_node, (const float*)p_node,
                              (const uint32_t*)p_WPh + 80, (const uint32_t*)p_WPl + 80,
                              160, 160, (float*)p_P, 768, (const float*)p_Pbase);
        k_edge_tc<<<(NE+127)/128, 512, 153600>>>(erow, ecol, eb1, eb2, mb1, attv, ln_eg, ln_eb);
        k_node<<<NN/16, 256>>>(x, nW1, nb1, ln_ng, ln_nb);
    }

    float* out = (float*)d_out;
    if (out_size >= NN*ND + NE*ED){
        cudaMemcpyAsync(out,         p_node, (size_t)NN*ND*sizeof(float), cudaMemcpyDeviceToDevice, 0);
        cudaMemcpyAsync(out + NN*ND, p_edge, (size_t)NE*ED*sizeof(float), cudaMemcpyDeviceToDevice, 0);
    } else if (out_size == NN*ND){
        cudaMemcpyAsync(out, p_node, (size_t)NN*ND*sizeof(float), cudaMemcpyDeviceToDevice, 0);
    } else {
        size_t nel = (size_t)((out_size < NE*ED) ? out_size : NE*ED);
        cudaMemcpyAsync(out, p_edge, nel*sizeof(float), cudaMemcpyDeviceToDevice, 0);
    }
}

// round 11
// speedup vs baseline: 1.0320x; 1.0168x over previous
#include <cuda_runtime.h>
#include <cuda_bf16.h>
#include <math.h>
#include <stdint.h>

#define NN 50000
#define NE 200000
#define ND 160
#define ED 64
#define RD 8
#define HD 256
#define EH 128

// ---------------- scratch (device globals; no runtime allocation) ----------
__device__ float g_init_edge[NE*ED];
__device__ float g_edge_lat [NE*ED];
__device__ float g_node_lat [NN*ND];
__device__ float g_msg      [NE*HD];
__device__ float g_logit    [NE];
__device__ float g_P        [(size_t)NN*768];
__device__ float g_Pbase    [(size_t)NN*768];
__device__ float g_Penc     [(size_t)NN*256];
__device__ uint32_t gWPh[768*160], gWPl[768*160];
__device__ uint32_t gWEh[256*80],  gWEl[256*80];
__device__ uint32_t gB1h[256*64],  gB1l[256*64];
__device__ uint32_t gB2h[64*128],  gB2l[64*128];
__device__ uint32_t gB3h[256*32],  gB3l[256*32];
__device__ int   g_deg      [NN];
__device__ int   g_rowptr   [NN+1];
__device__ int   g_fill     [NN];
__device__ int   g_eids     [NE];
__device__ int   g_part     [64];

// ---------------- helpers ----------------------------------------------------
__device__ __forceinline__ void split2(float x, float y, uint32_t& hi, uint32_t& lo){
    __nv_bfloat162 h = __floats2bfloat162_rn(x, y);
    hi = *(uint32_t*)&h;
    float rx = x - __bfloat162float(h.x);
    float ry = y - __bfloat162float(h.y);
    __nv_bfloat162 l = __floats2bfloat162_rn(rx, ry);
    lo = *(uint32_t*)&l;
}
__device__ __forceinline__ void mma_bf16(
    float& c0, float& c1, float& c2, float& c3,
    uint32_t a0, uint32_t a1, uint32_t a2, uint32_t a3, uint32_t b0, uint32_t b1)
{
    asm volatile(
        "mma.sync.aligned.m16n8k16.row.col.f32.bf16.bf16.f32 "
        "{%0,%1,%2,%3}, {%4,%5,%6,%7}, {%8,%9}, {%0,%1,%2,%3};"
        : "+f"(c0), "+f"(c1), "+f"(c2), "+f"(c3)
        : "r"(a0), "r"(a1), "r"(a2), "r"(a3), "r"(b0), "r"(b1));
}
__device__ __forceinline__ void ldsm_x4(uint32_t& r0, uint32_t& r1, uint32_t& r2, uint32_t& r3, uint32_t a){
    asm volatile("ldmatrix.sync.aligned.m8n8.x4.shared.b16 {%0,%1,%2,%3}, [%4];"
        : "=r"(r0), "=r"(r1), "=r"(r2), "=r"(r3) : "r"(a));
}

// ---------------- CSR build --------------------------------------------------
__global__ void k_hist(const int* __restrict__ row){
    int e = blockIdx.x*blockDim.x + threadIdx.x;
    if (e < NE) atomicAdd(&g_deg[row[e]], 1);
}

__global__ void k_scan1(){
    __shared__ int ss[256];
    int b = blockIdx.x, base = b*1024, tid = threadIdx.x;
    int v[4], tsum = 0;
#pragma unroll
    for (int r = 0; r < 4; r++){
        int idx = base + tid*4 + r;
        v[r] = (idx < NN) ? g_deg[idx] : 0;
        tsum += v[r];
    }
    ss[tid] = tsum; __syncthreads();
    for (int off = 1; off < 256; off <<= 1){
        int add = (tid >= off) ? ss[tid-off] : 0;
        __syncthreads();
        ss[tid] += add;
        __syncthreads();
    }
    int run = ss[tid] - tsum;
#pragma unroll
    for (int r = 0; r < 4; r++){
        int idx = base + tid*4 + r;
        if (idx < NN) g_rowptr[idx] = run;
        run += v[r];
    }
    if (tid == 255) g_part[b] = ss[255];
}

__global__ void k_scan2(){
    if (threadIdx.x == 0){
        int run = 0;
        for (int i = 0; i < 49; i++){ int t = g_part[i]; g_part[i] = run; run += t; }
    }
}

__global__ void k_scan3(){
    int i = blockIdx.x*blockDim.x + threadIdx.x;
    if (i < NN) g_rowptr[i] += g_part[i >> 10];
    if (i == 0) g_rowptr[NN] = NE;
}

__global__ void k_scatter(const int* __restrict__ row){
    int e = blockIdx.x*blockDim.x + threadIdx.x;
    if (e < NE){
        int p = atomicAdd(&g_fill[row[e]], 1);
        g_eids[p] = e;
    }
}

// ---------------- pack all weight tables (bf16 hi/lo, K-major) ---------------
__global__ void k_prep(const float* __restrict__ eW1, const float* __restrict__ mW1,
                       const float* __restrict__ encW1, const float* __restrict__ eW2)
{
    int i = blockIdx.x*blockDim.x + threadIdx.x;
    if (i < 768*160){
        int n = i/160, w = i - n*160, k = w*2;
        float f0, f1;
        if (n < 256){ f0 = eW1[k*256+n]; f1 = eW1[(k+1)*256+n]; }
        else if (n < 512){ int nn = n-256; f0 = eW1[(320+k)*256+nn]; f1 = eW1[(321+k)*256+nn]; }
        else { int nn = n-512; f0 = mW1[k*256+nn]; f1 = mW1[(k+1)*256+nn]; }
        split2(f0, f1, gWPh[i], gWPl[i]);
    }
    if (i < 256*80){
        int n = i/80, w = i - n*80, k = w*2;
        float f0, f1;
        if (n < 128){ f0 = encW1[k*128+n]; f1 = encW1[(k+1)*128+n]; }
        else { int nn = n-128; f0 = encW1[(160+k)*128+nn]; f1 = encW1[(161+k)*128+nn]; }
        split2(f0, f1, gWEh[i], gWEl[i]);
    }
    if (i < 256*64){
        int n = i/64, w = i - n*64, k = w*2;
        split2(eW1[(640+k)*256+n], eW1[(641+k)*256+n], gB1h[i], gB1l[i]);
    }
    if (i < 64*128){
        int n = i/128, w = i - n*128, k = w*2;
        split2(eW2[k*64+n], eW2[(k+1)*64+n], gB2h[i], gB2l[i]);
    }
    if (i < 256*32){
        int n = i/32, w = i - n*32, k = w*2;
        split2(mW1[(320+k)*256+n], mW1[(321+k)*256+n], gB3h[i], gB3l[i]);
    }
}

// ---------------- bf16 3-split dense GEMM (m16n8k16) -------------------------
__global__ __launch_bounds__(256,2) void k_gemm_bf(
    const float* __restrict__ A0, const float* __restrict__ A1,
    const uint32_t* __restrict__ Bh, const uint32_t* __restrict__ Bl,
    int K, int bstrW,
    float* __restrict__ out, int ostride, const float* __restrict__ base)
{
    __shared__ uint32_t sAh[128*20], sAl[128*20], sBh[128*20], sBl[128*20];
    const int tid = threadIdx.x, wid = tid>>5, lane = tid&31;
    const int gid = lane>>2, tq = lane&3;
    const int warp_m = (wid & 1)*64, warp_n = (wid >> 1)*32;
    const int m0 = blockIdx.x*128, n0 = blockIdx.y*128;

    float c[4][4][4];
#pragma unroll
    for (int i = 0; i < 4; i++)
#pragma unroll
        for (int j = 0; j < 4; j++)
#pragma unroll
            for (int r = 0; r < 4; r++) c[i][j][r] = 0.f;

    const int nk = K >> 5;
    for (int ch = 0; ch < nk; ch++){
        const int kc = ch*32;
        const float* A = (kc < 160) ? A0 : A1;
        const int ac = (kc < 160) ? kc : (kc - 160);
#pragma unroll
        for (int p = 0; p < 4; p++){
            int lin = tid + p*256;
            int row = lin>>3, f4 = lin&7;
            int gm = m0 + row;
            float4 v = make_float4(0.f,0.f,0.f,0.f);
            if (gm < NN) v = *(const float4*)&A[(size_t)gm*ND + ac + f4*4];
            uint32_t h0,l0,h1,l1;
            split2(v.x, v.y, h0, l0);
            split2(v.z, v.w, h1, l1);
            sAh[row*20 + f4*2]   = h0; sAh[row*20 + f4*2+1] = h1;
            sAl[row*20 + f4*2]   = l0; sAl[row*20 + f4*2+1] = l1;
        }
#pragma unroll
        for (int p = 0; p < 2; p++){
            int lin = tid + p*256;
            int row = lin>>2, q = lin&3;
            size_t gofs = (size_t)(n0+row)*bstrW + (kc>>1) + q*4;
            *(uint4*)&sBh[row*20 + q*4] = *(const uint4*)&Bh[gofs];
            *(uint4*)&sBl[row*20 + q*4] = *(const uint4*)&Bl[gofs];
        }
        __syncthreads();
#pragma unroll
        for (int s = 0; s < 2; s++){
            const int kb = s*8 + tq;
            uint32_t bh0[4], bh1[4], bl0[4], bl1[4];
#pragma unroll
            for (int nt = 0; nt < 4; nt++){
                int nr = warp_n + nt*8 + gid;
                bh0[nt] = sBh[nr*20 + kb]; bh1[nt] = sBh[nr*20 + kb + 4];
                bl0[nt] = sBl[nr*20 + kb]; bl1[nt] = sBl[nr*20 + kb + 4];
            }
#pragma unroll
            for (int mt = 0; mt < 4; mt++){
                int ar = warp_m + mt*16 + gid;
                uint32_t ah0 = sAh[ar*20+kb],     ah1 = sAh[(ar+8)*20+kb];
                uint32_t ah2 = sAh[ar*20+kb+4],   ah3 = sAh[(ar+8)*20+kb+4];
                uint32_t al0 = sAl[ar*20+kb],     al1 = sAl[(ar+8)*20+kb];
                uint32_t al2 = sAl[ar*20+kb+4],   al3 = sAl[(ar+8)*20+kb+4];
#pragma unroll
                for (int nt = 0; nt < 4; nt++){
                    mma_bf16(c[mt][nt][0], c[mt][nt][1], c[mt][nt][2], c[mt][nt][3],
                             ah0, ah1, ah2, ah3, bh0[nt], bh1[nt]);
                    mma_bf16(c[mt][nt][0], c[mt][nt][1], c[mt][nt][2], c[mt][nt][3],
                             ah0, ah1, ah2, ah3, bl0[nt], bl1[nt]);
                    mma_bf16(c[mt][nt][0], c[mt][nt][1], c[mt][nt][2], c[mt][nt][3],
                             al0, al1, al2, al3, bh0[nt], bh1[nt]);
                }
            }
        }
        __syncthreads();
    }

#pragma unroll
    for (int mt = 0; mt < 4; mt++){
        int r0 = m0 + warp_m + mt*16 + gid;
        int r1 = r0 + 8;
#pragma unroll
        for (int nt = 0; nt < 4; nt++){
            int gn = n0 + warp_n + nt*8 + tq*2;
            if (r0 < NN){
                float2 v = make_float2(c[mt][nt][0], c[mt][nt][1]);
                if (base){ float2 b = *(const float2*)&base[(size_t)r0*ostride + gn]; v.x += b.x; v.y += b.y; }
                *(float2*)&out[(size_t)r0*ostride + gn] = v;
            }
            if (r1 < NN){
                float2 v = make_float2(c[mt][nt][2], c[mt][nt][3]);
                if (base){ float2 b = *(const float2*)&base[(size_t)r1*ostride + gn]; v.x += b.x; v.y += b.y; }
                *(float2*)&out[(size_t)r1*ostride + gn] = v;
            }
        }
    }
}

// ---------------- fused edge kernel: ldmatrix A-operands ---------------------
__global__ __launch_bounds__(512,1) void k_edge_tc(
    const int* __restrict__ row, const int* __restrict__ col,
    const float* __restrict__ eb1, const float* __restrict__ eb2,
    const float* __restrict__ mb1, const float* __restrict__ attv,
    const float* __restrict__ lgE, const float* __restrict__ lbE)
{
    extern __shared__ uint32_t esm[];
    uint32_t* Ah  = esm;              // [128][68]
    uint32_t* Al  = esm + 8704;
    uint32_t* B1h = esm + 17408;      // [256][20]
    uint32_t* B1l = esm + 22528;
    uint32_t* Hh  = esm;              // [128][132] overlay (phase2)
    uint32_t* Hl  = esm + 16896;
    uint32_t* B2h = esm + 33792;      // [64][36]
    uint32_t* B2l = esm + 36096;
    uint32_t* NEh = esm;              // [128][36] overlay
    uint32_t* NEl = esm + 4608;
    uint32_t* B3h = esm + 9216;       // [256][36]
    uint32_t* B3l = esm + 18432;
    __shared__ int sR[128], sC[128];
    __shared__ float sAtt[256];
    __shared__ float sLog[128];
    __shared__ float sSum[128], sSq[128], sMu[128], sInv[128];

    const int tid = threadIdx.x, wid = tid>>5, lane = tid&31;
    const int gid = lane>>2, tq = lane&3;
    const int warp_m  = (wid & 1)*64;
    const int warp_n  = (wid >> 1)*32;
    const int warp_n2 = (wid >> 1)*8;
    const int e0 = blockIdx.x*128;

    // ldmatrix per-lane address bases (lane 0-15: rows +0..15 at k-base;
    // lane 16-31: same rows at k-base+4 words) -> r0..r3 = ah0..ah3 layout
    const int lrow = lane & 15;
    const int lkh  = (lane >> 4) << 2;       // word offset 0 or 4
    const uint32_t aAh = (uint32_t)__cvta_generic_to_shared(Ah);
    const uint32_t aAl = (uint32_t)__cvta_generic_to_shared(Al);
    const uint32_t aHh = (uint32_t)__cvta_generic_to_shared(Hh);
    const uint32_t aHl = (uint32_t)__cvta_generic_to_shared(Hl);
    const uint32_t aNh = (uint32_t)__cvta_generic_to_shared(NEh);
    const uint32_t aNl = (uint32_t)__cvta_generic_to_shared(NEl);
    uint32_t offA[4], offH[4], offN[4];
#pragma unroll
    for (int mt = 0; mt < 4; mt++){
        int r = warp_m + mt*16 + lrow;
        offA[mt] = (uint32_t)((r*68  + lkh) * 4);
        offH[mt] = (uint32_t)((r*132 + lkh) * 4);
        offN[mt] = (uint32_t)((r*36  + lkh) * 4);
    }

    if (tid < 128){
        int ge = e0 + tid;
        sR[tid] = (ge < NE) ? row[ge] : 0;
        sC[tid] = (ge < NE) ? col[ge] : 0;
        sLog[tid] = 0.f; sSum[tid] = 0.f; sSq[tid] = 0.f;
    }
    if (tid < 256) sAtt[tid] = attv[tid];
    __syncthreads();

    // ---- phase 1: stage A + C init from P gathers ---------------------------
    for (int lin = tid; lin < 8192; lin += 512){
        int r = lin>>6, w = lin&63, k = w*2;
        float2 v = make_float2(0.f, 0.f);
        if (e0 + r < NE)
            v = (k < 64) ? *(const float2*)&g_init_edge[(size_t)(e0+r)*ED + k]
                         : *(const float2*)&g_edge_lat [(size_t)(e0+r)*ED + (k-64)];
        split2(v.x, v.y, Ah[r*68+w], Al[r*68+w]);
    }
    float c1[4][4][4];
#pragma unroll
    for (int mt = 0; mt < 4; mt++){
        int rA = warp_m + mt*16 + gid, rB = rA + 8;
        size_t prA = (size_t)sR[rA]*768, pcA = (size_t)sC[rA]*768;
        size_t prB = (size_t)sR[rB]*768, pcB = (size_t)sC[rB]*768;
#pragma unroll
        for (int nt = 0; nt < 4; nt++){
            int cn = warp_n + nt*8 + tq*2;
            float2 b  = *(const float2*)&eb1[cn];
            float2 a1 = *(const float2*)&g_P[prA + cn];
            float2 a2 = *(const float2*)&g_P[pcA + 256 + cn];
            float2 a3 = *(const float2*)&g_P[prB + cn];
            float2 a4 = *(const float2*)&g_P[pcB + 256 + cn];
            c1[mt][nt][0] = a1.x + a2.x + b.x;
            c1[mt][nt][1] = a1.y + a2.y + b.y;
            c1[mt][nt][2] = a3.x + a4.x + b.x;
            c1[mt][nt][3] = a3.y + a4.y + b.y;
        }
    }
    __syncthreads();

#pragma unroll
    for (int ch = 0; ch < 4; ch++){
        for (int lin = tid; lin < 1024; lin += 512){
            int r = lin>>2, q = lin&3;
            size_t gofs = (size_t)r*64 + ch*16 + q*4;
            *(uint4*)&B1h[r*20 + q*4] = *(const uint4*)&gB1h[gofs];
            *(uint4*)&B1l[r*20 + q*4] = *(const uint4*)&gB1l[gofs];
        }
        __syncthreads();
#pragma unroll
        for (int s = 0; s < 2; s++){
            int kb = s*8 + tq;
            uint32_t kw = (uint32_t)((ch*16 + s*8) * 4);
            uint32_t bh0[4], bh1[4], bl0[4], bl1[4];
#pragma unroll
            for (int nt = 0; nt < 4; nt++){
                int nr = warp_n + nt*8 + gid;
                bh0[nt] = B1h[nr*20+kb]; bh1[nt] = B1h[nr*20+kb+4];
                bl0[nt] = B1l[nr*20+kb]; bl1[nt] = B1l[nr*20+kb+4];
            }
#pragma unroll
            for (int mt = 0; mt < 4; mt++){
                uint32_t ah0,ah1,ah2,ah3, al0,al1,al2,al3;
                ldsm_x4(ah0,ah1,ah2,ah3, aAh + offA[mt] + kw);
                ldsm_x4(al0,al1,al2,al3, aAl + offA[mt] + kw);
#pragma unroll
                for (int nt = 0; nt < 4; nt++){
                    mma_bf16(c1[mt][nt][0],c1[mt][nt][1],c1[mt][nt][2],c1[mt][nt][3],
                             ah0,ah1,ah2,ah3, bh0[nt],bh1[nt]);
                    mma_bf16(c1[mt][nt][0],c1[mt][nt][1],c1[mt][nt][2],c1[mt][nt][3],
                             ah0,ah1,ah2,ah3, bl0[nt],bl1[nt]);
                    mma_bf16(c1[mt][nt][0],c1[mt][nt][1],c1[mt][nt][2],c1[mt][nt][3],
                             al0,al1,al2,al3, bh0[nt],bh1[nt]);
                }
            }
        }
        __syncthreads();
    }

    // write hidden (relu, bf16 split) over A/B1 region
#pragma unroll
    for (int mt = 0; mt < 4; mt++){
        int rA = warp_m + mt*16 + gid, rB = rA + 8;
#pragma unroll
        for (int nt = 0; nt < 4; nt++){
            int wcol = (warp_n>>1) + nt*4 + tq;
            float v0 = fmaxf(c1[mt][nt][0], 0.f), v1 = fmaxf(c1[mt][nt][1], 0.f);
            float v2 = fmaxf(c1[mt][nt][2], 0.f), v3 = fmaxf(c1[mt][nt][3], 0.f);
            split2(v0, v1, Hh[rA*132+wcol], Hl[rA*132+wcol]);
            split2(v2, v3, Hh[rB*132+wcol], Hl[rB*132+wcol]);
        }
    }
    __syncthreads();

    // ---- phase 2 ------------------------------------------------------------
    float c2[4][4];
#pragma unroll
    for (int mt = 0; mt < 4; mt++){
        float2 b = *(const float2*)&eb2[warp_n2 + tq*2];
        c2[mt][0] = b.x; c2[mt][1] = b.y; c2[mt][2] = b.x; c2[mt][3] = b.y;
    }
#pragma unroll
    for (int ch = 0; ch < 4; ch++){
        {
            int r = tid>>3, q = tid&7;
            size_t gofs = (size_t)r*128 + ch*32 + q*4;
            *(uint4*)&B2h[r*36 + q*4] = *(const uint4*)&gB2h[gofs];
            *(uint4*)&B2l[r*36 + q*4] = *(const uint4*)&gB2l[gofs];
        }
        __syncthreads();
#pragma unroll
        for (int s = 0; s < 4; s++){
            int kb = s*8 + tq;
            uint32_t kw = (uint32_t)((ch*32 + s*8) * 4);
            int nr = warp_n2 + gid;
            uint32_t bh0 = B2h[nr*36+kb], bh1 = B2h[nr*36+kb+4];
            uint32_t bl0 = B2l[nr*36+kb], bl1 = B2l[nr*36+kb+4];
#pragma unroll
            for (int mt = 0; mt < 4; mt++){
                uint32_t ah0,ah1,ah2,ah3, al0,al1,al2,al3;
                ldsm_x4(ah0,ah1,ah2,ah3, aHh + offH[mt] + kw);
                ldsm_x4(al0,al1,al2,al3, aHl + offH[mt] + kw);
                mma_bf16(c2[mt][0],c2[mt][1],c2[mt][2],c2[mt][3], ah0,ah1,ah2,ah3, bh0,bh1);
                mma_bf16(c2[mt][0],c2[mt][1],c2[mt][2],c2[mt][3], ah0,ah1,ah2,ah3, bl0,bl1);
                mma_bf16(c2[mt][0],c2[mt][1],c2[mt][2],c2[mt][3], al0,al1,al2,al3, bh0,bh1);
            }
        }
        __syncthreads();
    }

    // ---- NE pack + LN stats; stage full B3 (stride 36) -----------------------
#pragma unroll
    for (int mt = 0; mt < 4; mt++){
        int rA = warp_m + mt*16 + gid, rB = rA + 8;
        int cn = warp_n2 + tq*2;
        int wcol = (warp_n2>>1) + tq;
        split2(c2[mt][0], c2[mt][1], NEh[rA*36+wcol], NEl[rA*36+wcol]);
        split2(c2[mt][2], c2[mt][3], NEh[rB*36+wcol], NEl[rB*36+wcol]);
        float2 iA = make_float2(0.f,0.f), iB = make_float2(0.f,0.f);
        if (e0 + rA < NE) iA = *(const float2*)&g_init_edge[(size_t)(e0+rA)*ED + cn];
        if (e0 + rB < NE) iB = *(const float2*)&g_init_edge[(size_t)(e0+rB)*ED + cn];
        c2[mt][0] += iA.x; c2[mt][1] += iA.y;
        c2[mt][2] += iB.x; c2[mt][3] += iB.y;
        atomicAdd(&sSum[rA], c2[mt][0] + c2[mt][1]);
        atomicAdd(&sSq [rA], c2[mt][0]*c2[mt][0] + c2[mt][1]*c2[mt][1]);
        atomicAdd(&sSum[rB], c2[mt][2] + c2[mt][3]);
        atomicAdd(&sSq [rB], c2[mt][2]*c2[mt][2] + c2[mt][3]*c2[mt][3]);
    }
    for (int lin = tid; lin < 2048; lin += 512){
        int r = lin>>3, q = lin&7;
        size_t gofs = (size_t)r*32 + q*4;
        *(uint4*)&B3h[r*36 + q*4] = *(const uint4*)&gB3h[gofs];
        *(uint4*)&B3l[r*36 + q*4] = *(const uint4*)&gB3l[gofs];
    }
    float c3[4][4][4];
#pragma unroll
    for (int mt = 0; mt < 4; mt++){
        int rA = warp_m + mt*16 + gid, rB = rA + 8;
        size_t pcA = (size_t)sC[rA]*768, pcB = (size_t)sC[rB]*768;
#pragma unroll
        for (int nt = 0; nt < 4; nt++){
            int cn = warp_n + nt*8 + tq*2;
            float2 b  = *(const float2*)&mb1[cn];
            float2 a1 = *(const float2*)&g_P[pcA + 512 + cn];
            float2 a2 = *(const float2*)&g_P[pcB + 512 + cn];
            c3[mt][nt][0] = a1.x + b.x; c3[mt][nt][1] = a1.y + b.y;
            c3[mt][nt][2] = a2.x + b.x; c3[mt][nt][3] = a2.y + b.y;
        }
    }
    __syncthreads();

    if (tid < 128){
        float mu = sSum[tid] * (1.f/ED);
        float var = sSq[tid] * (1.f/ED) - mu*mu;
        sMu[tid] = mu;
        sInv[tid] = rsqrtf(var + 1e-5f);
    }
    __syncthreads();

#pragma unroll
    for (int mt = 0; mt < 4; mt++){
        int rA = warp_m + mt*16 + gid, rB = rA + 8;
        int cn = warp_n2 + tq*2;
        float g0 = lgE[cn], g1 = lgE[cn+1], b0 = lbE[cn], b1 = lbE[cn+1];
        if (e0 + rA < NE){
            float mu = sMu[rA], inv = sInv[rA];
            *(float2*)&g_edge_lat[(size_t)(e0+rA)*ED + cn] =
                make_float2((c2[mt][0]-mu)*inv*g0 + b0, (c2[mt][1]-mu)*inv*g1 + b1);
        }
        if (e0 + rB < NE){
            float mu = sMu[rB], inv = sInv[rB];
            *(float2*)&g_edge_lat[(size_t)(e0+rB)*ED + cn] =
                make_float2((c2[mt][2]-mu)*inv*g0 + b0, (c2[mt][3]-mu)*inv*g1 + b1);
        }
    }

    // ---- phase 3 MMA loop ----------------------------------------------------
#pragma unroll
    for (int s = 0; s < 4; s++){
        int ka = s*8 + tq;
        uint32_t kw = (uint32_t)((s*8) * 4);
        uint32_t bh0[4], bh1[4], bl0[4], bl1[4];
#pragma unroll
        for (int nt = 0; nt < 4; nt++){
            int nr = warp_n + nt*8 + gid;
            bh0[nt] = B3h[nr*36+ka]; bh1[nt] = B3h[nr*36+ka+4];
            bl0[nt] = B3l[nr*36+ka]; bl1[nt] = B3l[nr*36+ka+4];
        }
#pragma unroll
        for (int mt = 0; mt < 4; mt++){
            uint32_t ah0,ah1,ah2,ah3, al0,al1,al2,al3;
            ldsm_x4(ah0,ah1,ah2,ah3, aNh + offN[mt] + kw);
            ldsm_x4(al0,al1,al2,al3, aNl + offN[mt] + kw);
#pragma unroll
            for (int nt = 0; nt < 4; nt++){
                mma_bf16(c3[mt][nt][0],c3[mt][nt][1],c3[mt][nt][2],c3[mt][nt][3],
                         ah0,ah1,ah2,ah3, bh0[nt],bh1[nt]);
                mma_bf16(c3[mt][nt][0],c3[mt][nt][1],c3[mt][nt][2],c3[mt][nt][3],
                         ah0,ah1,ah2,ah3, bl0[nt],bl1[nt]);
                mma_bf16(c3[mt][nt][0],c3[mt][nt][1],c3[mt][nt][2],c3[mt][nt][3],
                         al0,al1,al2,al3, bh0[nt],bh1[nt]);
            }
        }
    }

    // epilogue: relu -> g_msg, attention partial dot, logit
    float pa[4][2];
#pragma unroll
    for (int mt = 0; mt < 4; mt++){ pa[mt][0] = 0.f; pa[mt][1] = 0.f; }
#pragma unroll
    for (int mt = 0; mt < 4; mt++){
        int rA = warp_m + mt*16 + gid, rB = rA + 8;
#pragma unroll
        for (int nt = 0; nt < 4; nt++){
            int cn = warp_n + nt*8 + tq*2;
            float av0 = sAtt[cn], av1 = sAtt[cn+1];
            float v0 = fmaxf(c3[mt][nt][0], 0.f), v1 = fmaxf(c3[mt][nt][1], 0.f);
            float v2 = fmaxf(c3[mt][nt][2], 0.f), v3 = fmaxf(c3[mt][nt][3], 0.f);
            if (e0 + rA < NE)
                *(float2*)&g_msg[(size_t)(e0+rA)*HD + cn] = make_float2(v0, v1);
            if (e0 + rB < NE)
                *(float2*)&g_msg[(size_t)(e0+rB)*HD + cn] = make_float2(v2, v3);
            pa[mt][0] += v0*av0 + v1*av1;
            pa[mt][1] += v2*av0 + v3*av1;
        }
    }
#pragma unroll
    for (int off = 1; off <= 2; off <<= 1){
#pragma unroll
        for (int mt = 0; mt < 4; mt++){
            pa[mt][0] += __shfl_xor_sync(0xffffffffu, pa[mt][0], off, 4);
            pa[mt][1] += __shfl_xor_sync(0xffffffffu, pa[mt][1], off, 4);
        }
    }
    if (tq == 0){
#pragma unroll
        for (int mt = 0; mt < 4; mt++){
            atomicAdd(&sLog[warp_m + mt*16 + gid],     pa[mt][0]);
            atomicAdd(&sLog[warp_m + mt*16 + gid + 8], pa[mt][1]);
        }
    }
    __syncthreads();
    if (tid < 128 && e0 + tid < NE){
        float p = sLog[tid];
        g_logit[e0+tid] = (p > 0.f) ? p : 0.2f*p;
    }
}

// ---------------- edge encoder tail: per-edge part (FFMA, small) -------------
__global__ __launch_bounds__(256,2) void k_enc_edge(
    const float* __restrict__ ea,
    const int* __restrict__ row, const int* __restrict__ col,
    const float* __restrict__ encW1, const float* __restrict__ encb1,
    const float* __restrict__ encW2, const float* __restrict__ encb2)
{
    __shared__ float As[64*9];
    __shared__ float Bs[16*64];
    __shared__ float Hid[64*132];
    __shared__ int sR[64], sC[64];

    const int e0 = blockIdx.x*64;
    const int tid = threadIdx.x, ty = tid>>4, tx = tid&15;
    if (tid < 64){ sR[tid] = row[e0+tid]; sC[tid] = col[e0+tid]; }
    __syncthreads();

    float c[4][8];
#pragma unroll
    for (int i = 0; i < 4; i++){
        int r = ty*4+i;
#pragma unroll
        for (int j = 0; j < 8; j++){
            int n = tx + 16*j;
            c[i][j] = g_Penc[(size_t)sR[r]*256 + n]
                    + g_Penc[(size_t)sC[r]*256 + 128 + n]
                    + encb1[n];
        }
    }
    for (int t = tid; t < 512; t += 256){
        int el = t>>3, kk = t&7;
        As[el*9+kk] = ea[(e0+el)*RD + kk];
    }
    for (int t = tid; t < 1024; t += 256){
        int kk = t>>7, n = t&127;
        Bs[t] = encW1[(320+kk)*EH + n];
    }
    __syncthreads();
#pragma unroll
    for (int kk = 0; kk < 8; kk++){
        float a0 = As[(ty*4+0)*9+kk], a1 = As[(ty*4+1)*9+kk];
        float a2 = As[(ty*4+2)*9+kk], a3 = As[(ty*4+3)*9+kk];
#pragma unroll
        for (int j = 0; j < 8; j++){
            float b = Bs[kk*128 + tx + 16*j];
            c[0][j] += a0*b; c[1][j] += a1*b; c[2][j] += a2*b; c[3][j] += a3*b;
        }
    }
    __syncthreads();
#pragma unroll
    for (int i = 0; i < 4; i++)
#pragma unroll
        for (int j = 0; j < 8; j++){
            int n = tx + 16*j;
            Hid[(ty*4+i)*132 + n] = fmaxf(c[i][j], 0.f);
        }
    __syncthreads();

    float c2[4][4];
#pragma unroll
    for (int i = 0; i < 4; i++)
#pragma unroll
        for (int j = 0; j < 4; j++) c2[i][j] = encb2[tx+16*j];

    for (int kc = 0; kc < 128; kc += 16){
        for (int t = tid; t < 1024; t += 256){
            int kk = t>>6, n = t&63;
            Bs[t] = encW2[(kc+kk)*ED + n];
        }
        __syncthreads();
#pragma unroll
        for (int kk = 0; kk < 16; kk++){
            float a0 = Hid[(ty*4+0)*132 + kc+kk], a1 = Hid[(ty*4+1)*132 + kc+kk];
            float a2 = Hid[(ty*4+2)*132 + kc+kk], a3 = Hid[(ty*4+3)*132 + kc+kk];
#pragma unroll
            for (int j = 0; j < 4; j++){
                float b = Bs[kk*64 + tx + 16*j];
                c2[0][j] += a0*b; c2[1][j] += a1*b; c2[2][j] += a2*b; c2[3][j] += a3*b;
            }
        }
        __syncthreads();
    }
#pragma unroll
    for (int i = 0; i < 4; i++)
#pragma unroll
        for (int j = 0; j < 4; j++)
            g_init_edge[(size_t)(e0+ty*4+i)*ED + tx + 16*j] = c2[i][j];
}

// ---------------- node update: segment softmax + agg + MLP + LN -------------
__global__ __launch_bounds__(256,1) void k_node(
    const float* __restrict__ x, const float* __restrict__ nW1,
    const float* __restrict__ nb1,
    const float* __restrict__ lg, const float* __restrict__ lb)
{
    __shared__ float agg[16*260];
    __shared__ float Bs[32*160];

    const int n0 = blockIdx.x*16;
    const int tid = threadIdx.x, g = tid>>4, t = tid&15;
    const int n = n0 + g;
    const int beg = g_rowptr[n], end = g_rowptr[n+1];

    float m = -1e30f;
    for (int i = beg+t; i < end; i += 16) m = fmaxf(m, g_logit[g_eids[i]]);
#pragma unroll
    for (int off = 8; off >= 1; off >>= 1) m = fmaxf(m, __shfl_xor_sync(0xffffffffu, m, off, 16));

    float den = 0.f;
    for (int i = beg+t; i < end; i += 16) den += expf(g_logit[g_eids[i]] - m);
#pragma unroll
    for (int off = 8; off >= 1; off >>= 1) den += __shfl_xor_sync(0xffffffffu, den, off, 16);
    den += 1e-16f;
    float inv_den = 1.f/den;

    float acc[16];
#pragma unroll
    for (int q = 0; q < 16; q++) acc[q] = 0.f;
    for (int i = beg; i < end; i++){
        int e = g_eids[i];
        float w = expf(g_logit[e] - m) * inv_den;
        const float* mr = g_msg + (size_t)e*HD;
#pragma unroll
        for (int q = 0; q < 16; q++) acc[q] += w * mr[t + 16*q];
    }
#pragma unroll
    for (int q = 0; q < 16; q++) agg[g*260 + t + 16*q] = acc[q];
    __syncthreads();

    float c[10];
#pragma unroll
    for (int j = 0; j < 10; j++) c[j] = 0.f;
    for (int kc = 0; kc < 256; kc += 32){
        for (int t2 = tid; t2 < 5120; t2 += 256){
            int kk = t2/160, nn = t2 - kk*160;
            Bs[t2] = nW1[(kc+kk)*ND + nn];
        }
        __syncthreads();
#pragma unroll 4
        for (int kk = 0; kk < 32; kk++){
            float a = agg[g*260 + kc+kk];
#pragma unroll
            for (int j = 0; j < 10; j++) c[j] += a * Bs[kk*160 + t + 16*j];
        }
        __syncthreads();
    }

    float rv[10], s = 0.f, s2 = 0.f;
#pragma unroll
    for (int j = 0; j < 10; j++){
        int cc = t + 16*j;
        float v = x[n*ND + cc] + c[j] + nb1[cc];
        rv[j] = v; s += v; s2 += v*v;
    }
#pragma unroll
    for (int off = 8; off >= 1; off >>= 1){
        s  += __shfl_xor_sync(0xffffffffu, s,  off, 16);
        s2 += __shfl_xor_sync(0xffffffffu, s2, off, 16);
    }
    float mu  = s * (1.f/ND);
    float var = s2 * (1.f/ND) - mu*mu;
    float inv = rsqrtf(var + 1e-5f);
#pragma unroll
    for (int j = 0; j < 10; j++){
        int cc = t + 16*j;
        g_node_lat[n*ND + cc] = (rv[j] - mu)*inv*lg[cc] + lb[cc];
    }
}

// ---------------- launch -----------------------------------------------------
extern "C" void kernel_launch(void* const* d_in, const int* in_sizes, int n_in,
                              void* d_out, int out_size)
{
    const float* x     = (const float*)d_in[0];
    const float* ea    = (const float*)d_in[1];
    const float* encW1 = (const float*)d_in[2];
    const float* encb1 = (const float*)d_in[3];
    const float* encW2 = (const float*)d_in[4];
    const float* encb2 = (const float*)d_in[5];
    const float* eW1   = (const float*)d_in[6];
    const float* eb1   = (const float*)d_in[7];
    const float* eW2   = (const float*)d_in[8];
    const float* eb2   = (const float*)d_in[9];
    const float* mW1   = (const float*)d_in[10];
    const float* mb1   = (const float*)d_in[11];
    const float* attv  = (const float*)d_in[12];
    const float* nW1   = (const float*)d_in[13];
    const float* nb1   = (const float*)d_in[14];
    const float* ln_ng = (const float*)d_in[15];
    const float* ln_nb = (const float*)d_in[16];
    const float* ln_eg = (const float*)d_in[17];
    const float* ln_eb = (const float*)d_in[18];
    const int*   erow  = (const int*)d_in[19];
    const int*   ecol  = (const int*)d_in[20];

    void *p_deg, *p_rowptr, *p_fill, *p_node, *p_edge, *p_init, *p_P, *p_Pbase, *p_Penc;
    void *p_WEh, *p_WEl, *p_WPh, *p_WPl;
    cudaGetSymbolAddress(&p_deg,    g_deg);
    cudaGetSymbolAddress(&p_rowptr, g_rowptr);
    cudaGetSymbolAddress(&p_fill,   g_fill);
    cudaGetSymbolAddress(&p_node,   g_node_lat);
    cudaGetSymbolAddress(&p_edge,   g_edge_lat);
    cudaGetSymbolAddress(&p_init,   g_init_edge);
    cudaGetSymbolAddress(&p_P,      g_P);
    cudaGetSymbolAddress(&p_Pbase,  g_Pbase);
    cudaGetSymbolAddress(&p_Penc,   g_Penc);
    cudaGetSymbolAddress(&p_WEh,    gWEh);
    cudaGetSymbolAddress(&p_WEl,    gWEl);
    cudaGetSymbolAddress(&p_WPh,    gWPh);
    cudaGetSymbolAddress(&p_WPl,    gWPl);

    cudaFuncSetAttribute(k_edge_tc, cudaFuncAttributeMaxDynamicSharedMemorySize, 153600);

    static cudaStream_t s1 = nullptr;
    static cudaEvent_t evA = nullptr, evB = nullptr;
    if (s1 == nullptr){
        cudaStreamCreateWithFlags(&s1, cudaStreamNonBlocking);
        cudaEventCreateWithFlags(&evA, cudaEventDisableTiming);
        cudaEventCreateWithFlags(&evB, cudaEventDisableTiming);
    }

    // fork: CSR build on s1, GEMM prologue on stream 0
    cudaEventRecord(evA, 0);
    cudaStreamWaitEvent(s1, evA, 0);

    cudaMemsetAsync(p_deg, 0, NN*sizeof(int), s1);
    k_hist<<<(NE+255)/256, 256, 0, s1>>>(erow);
    k_scan1<<<49, 256, 0, s1>>>();
    k_scan2<<<1, 32, 0, s1>>>();
    k_scan3<<<(NN+255)/256, 256, 0, s1>>>();
    cudaMemcpyAsync(p_fill, p_rowptr, NN*sizeof(int), cudaMemcpyDeviceToDevice, s1);
    k_scatter<<<(NE+255)/256, 256, 0, s1>>>(erow);

    k_prep<<<480, 256>>>(eW1, mW1, encW1, eW2);
    {
        dim3 g((NN+127)/128, 6);
        k_gemm_bf<<<g, 256>>>(x, x, (const uint32_t*)p_WPh, (const uint32_t*)p_WPl,
                              160, 160, (float*)p_Pbase, 768, nullptr);
    }
    {
        dim3 g((NN+127)/128, 2);
        k_gemm_bf<<<g, 256>>>(x, x, (const uint32_t*)p_WEh, (const uint32_t*)p_WEl,
                              160, 80, (float*)p_Penc, 256, nullptr);
    }
    k_enc_edge<<<NE/64, 256>>>(ea, erow, ecol, encW1, encb1, encW2, encb2);

    cudaMemcpyAsync(p_node, x,      (size_t)NN*ND*sizeof(float), cudaMemcpyDeviceToDevice, 0);
    cudaMemcpyAsync(p_edge, p_init, (size_t)NE*ED*sizeof(float), cudaMemcpyDeviceToDevice, 0);

    cudaEventRecord(evB, s1);
    cudaStreamWaitEvent(0, evB, 0);

    for (int it = 0; it < 3; it++){
        dim3 g((NN+127)/128, 6);
        k_gemm_bf<<<g, 256>>>((const float*)p_node, (const float*)p_node,
                              (const uint32_t*)p_WPh + 80, (const uint32_t*)p_WPl + 80,
                              160, 160, (float*)p_P, 768, (const float*)p_Pbase);
        k_edge_tc<<<(NE+127)/128, 512, 153600>>>(erow, ecol, eb1, eb2, mb1, attv, ln_eg, ln_eb);
        k_node<<<NN/16, 256>>>(x, nW1, nb1, ln_ng, ln_nb);
    }

    float* out = (float*)d_out;
    if (out_size >= NN*ND + NE*ED){
        cudaMemcpyAsync(out,         p_node, (size_t)NN*ND*sizeof(float), cudaMemcpyDeviceToDevice, 0);
        cudaMemcpyAsync(out + NN*ND, p_edge, (size_t)NE*ED*sizeof(float), cudaMemcpyDeviceToDevice, 0);
    } else if (out_size == NN*ND){
        cudaMemcpyAsync(out, p_node, (size_t)NN*ND*sizeof(float), cudaMemcpyDeviceToDevice, 0);
    } else {
        size_t nel = (size_t)((out_size < NE*ED) ? out_size : NE*ED);
        cudaMemcpyAsync(out, p_edge, nel*sizeof(float), cudaMemcpyDeviceToDevice, 0);
    }
}